// round 10
// baseline (speedup 1.0000x reference)
#include <cuda_runtime.h>
#include <cuda_bf16.h>
#include <cstdint>

#define BATCH 8
#define HW    16384
#define HID   64

// ---------------- scratch (static device memory; no allocations) ----------------
__device__ float g_x1[BATCH * HW * HID];   // NHWC: [b][p][c]
__device__ float g_x2[BATCH * HW * HID];   // NHWC
__device__ float g_off[BATCH * HW * 18];   // [b][p][18]
__device__ float g_d [BATCH * HW * HID];   // NHWC

typedef unsigned long long u64;

__device__ __forceinline__ u64 pk2(float lo, float hi) {
    u64 r; asm("mov.b64 %0, {%1,%2};" : "=l"(r) : "f"(lo), "f"(hi)); return r;
}
__device__ __forceinline__ u64 f2fma(u64 a, u64 b, u64 c) {
    u64 d; asm("fma.rn.f32x2 %0,%1,%2,%3;" : "=l"(d) : "l"(a), "l"(b), "l"(c)); return d;
}
__device__ __forceinline__ u64 f2mul(u64 a, u64 b) {
    u64 d; asm("mul.rn.f32x2 %0,%1,%2;" : "=l"(d) : "l"(a), "l"(b)); return d;
}
__device__ __forceinline__ float silu_f(float v) {
    return __fdividef(v, 1.0f + __expf(-v));
}

// ---------------- mma.sync + ldmatrix helpers (baseline PTX) ----------------
__device__ __forceinline__ uint32_t smem_u32(const void* p) {
    uint32_t a;
    asm("{ .reg .u64 t; cvta.to.shared.u64 t, %1; cvt.u32.u64 %0, t; }" : "=r"(a) : "l"(p));
    return a;
}
__device__ __forceinline__ uint32_t bf2(float lo, float hi) {
    uint32_t r; asm("cvt.rn.bf16x2.f32 %0, %1, %2;" : "=r"(r) : "f"(hi), "f"(lo)); return r;
}
// split-bf16 of a float pair -> hi-pair u32 and lo-pair u32 (residuals)
__device__ __forceinline__ void split2(float a, float b, uint32_t& h, uint32_t& l) {
    h = bf2(a, b);
    float hf_lo = __uint_as_float(h << 16);
    float hf_hi = __uint_as_float(h & 0xFFFF0000u);
    l = bf2(a - hf_lo, b - hf_hi);
}
__device__ __forceinline__ void mma_bf16(float* d, const uint32_t* a, const uint32_t* bb) {
    asm volatile(
        "mma.sync.aligned.m16n8k16.row.col.f32.bf16.bf16.f32 "
        "{%0,%1,%2,%3}, {%4,%5,%6,%7}, {%8,%9}, {%0,%1,%2,%3};"
        : "+f"(d[0]), "+f"(d[1]), "+f"(d[2]), "+f"(d[3])
        : "r"(a[0]), "r"(a[1]), "r"(a[2]), "r"(a[3]), "r"(bb[0]), "r"(bb[1]));
}
__device__ __forceinline__ void ldsm4(uint32_t* r, uint32_t a) {
    asm volatile("ldmatrix.sync.aligned.m8n8.x4.shared.b16 {%0,%1,%2,%3}, [%4];"
        : "=r"(r[0]), "=r"(r[1]), "=r"(r[2]), "=r"(r[3]) : "r"(a));
}
__device__ __forceinline__ void ldsm2(uint32_t* r, uint32_t a) {
    asm volatile("ldmatrix.sync.aligned.m8n8.x2.shared.b16 {%0,%1}, [%2];"
        : "=r"(r[0]), "=r"(r[1]) : "r"(a));
}

// smem tile geometry: 128 rows x 64 bf16 cols, row stride 144 bytes (72 bf16)
// -> every 8-lane ldmatrix phase walks banks with a shift of 4/row: conflict-free
#define TS      144
#define TILE_B  (128 * TS)          // 18432
#define SM_AHI  0
#define SM_ALO  (TILE_B)
#define SM_BHI  (2 * TILE_B)
#define SM_BLO  (3 * TILE_B)
#define SM_MMA_TOTAL (4 * TILE_B)   // 73728 bytes -> 2 CTAs/SM

// GEMM core for one K=64 stage via ldmatrix fragments.
// aHi/aLo/bHi/bLo are per-thread lane-resolved base addresses (see callers).
__device__ __forceinline__ void mma_stage_ldsm(
    uint32_t aHi, uint32_t aLo, uint32_t bHi, uint32_t bLo, float acc[2][8][4])
{
    #pragma unroll
    for (int kk = 0; kk < 4; kk++) {
        const uint32_t kb = kk * 32;
        uint32_t ah[2][4], al[2][4];
        ldsm4(ah[0], aHi + kb);
        ldsm4(ah[1], aHi + kb + 16 * TS);
        ldsm4(al[0], aLo + kb);
        ldsm4(al[1], aLo + kb + 16 * TS);
        #pragma unroll
        for (int j = 0; j < 8; j++) {
            uint32_t bh[2], bl[2];
            ldsm2(bh, bHi + kb + j * 8 * TS);
            ldsm2(bl, bLo + kb + j * 8 * TS);
            #pragma unroll
            for (int i = 0; i < 2; i++) {
                mma_bf16(acc[i][j], ah[i], bh);
                mma_bf16(acc[i][j], ah[i], bl);
                mma_bf16(acc[i][j], al[i], bh);
            }
        }
    }
}

// ======================= K1: fused dual 1x1 GEMM + SiLU (mma.sync) =======================
// D[p][o] = sum_c x[b][c][p] * Wcat[o][c];  o<64 -> x1 (s1,b1), o>=64 -> x2 (s2,b2)
__global__ void __launch_bounds__(256) k1_mma(
    const float* __restrict__ x,
    const float* __restrict__ w1, const float* __restrict__ s1, const float* __restrict__ b1,
    const float* __restrict__ w2, const float* __restrict__ s2, const float* __restrict__ b2)
{
    extern __shared__ char smem[];
    const int t = threadIdx.x, wid = t >> 5, lane = t & 31;
    const int g = lane >> 2, tg = lane & 3;
    const int wm = wid & 3, wn = wid >> 2;
    const int b = blockIdx.y, P = blockIdx.x << 7;

    const uint32_t sb  = smem_u32(smem);
    const uint32_t aHi = sb + SM_AHI + (wm * 32 + (lane & 15)) * TS + (lane >> 4) * 16;
    const uint32_t aLo = aHi + TILE_B;
    const uint32_t bHi = sb + SM_BHI + (wn * 64 + (lane & 7)) * TS + ((lane >> 3) & 1) * 16;
    const uint32_t bLo = bHi + TILE_B;

    float acc[2][8][4];
    #pragma unroll
    for (int i = 0; i < 2; i++)
        #pragma unroll
        for (int j = 0; j < 8; j++)
            #pragma unroll
            for (int q = 0; q < 4; q++) acc[i][j][q] = 0.f;

    const float* xb = x + b * (128 * HW) + P;

    #pragma unroll 1
    for (int s = 0; s < 2; s++) {
        // A: transpose x[c][p] -> rows = pixels, cols = channels (stage s: c in [s*64, s*64+64))
        for (int e = t; e < 2048; e += 256) {
            int r = e & 127, c4 = (e >> 7) << 2;
            const float* src = xb + (s * 64 + c4) * HW + r;
            float v0 = src[0], v1 = src[HW], v2 = src[2 * HW], v3 = src[3 * HW];
            uint32_t h01, l01, h23, l23;
            split2(v0, v1, h01, l01);
            split2(v2, v3, h23, l23);
            int off = r * TS + c4 * 2;
            *(uint32_t*)(smem + SM_AHI + off)     = h01;
            *(uint32_t*)(smem + SM_AHI + off + 4) = h23;
            *(uint32_t*)(smem + SM_ALO + off)     = l01;
            *(uint32_t*)(smem + SM_ALO + off + 4) = l23;
        }
        // B: Wcat rows, K-major direct
        for (int e = t; e < 2048; e += 256) {
            int o = e >> 4, c4 = (e & 15) << 2;
            const float* src = (o < 64 ? w1 + o * 128 : w2 + (o - 64) * 128) + s * 64 + c4;
            float4 v = *(const float4*)src;
            uint32_t h01, l01, h23, l23;
            split2(v.x, v.y, h01, l01);
            split2(v.z, v.w, h23, l23);
            int off = o * TS + c4 * 2;
            *(uint32_t*)(smem + SM_BHI + off)     = h01;
            *(uint32_t*)(smem + SM_BHI + off + 4) = h23;
            *(uint32_t*)(smem + SM_BLO + off)     = l01;
            *(uint32_t*)(smem + SM_BLO + off + 4) = l23;
        }
        __syncthreads();
        mma_stage_ldsm(aHi, aLo, bHi, bLo, acc);
        __syncthreads();
    }

    // Epilogue: acc[i][j] is 16x8 frag at (row wm*32+i*16, col wn*64+j*8)
    #pragma unroll
    for (int i = 0; i < 2; i++) {
        #pragma unroll
        for (int j = 0; j < 8; j++) {
            int o = wn * 64 + j * 8 + 2 * tg;
            bool first = (o < 64);
            int ob = o & 63;
            const float* sv = first ? s1 : s2;
            const float* bv = first ? b1 : b2;
            float sc0 = sv[ob], sc1 = sv[ob + 1];
            float bc0 = bv[ob], bc1 = bv[ob + 1];
            float* base = (first ? g_x1 : g_x2) + (b * HW) * 64;
            int p0 = P + wm * 32 + i * 16 + g;
            float2 r0, r1;
            r0.x = silu_f(fmaf(acc[i][j][0], sc0, bc0));
            r0.y = silu_f(fmaf(acc[i][j][1], sc1, bc1));
            r1.x = silu_f(fmaf(acc[i][j][2], sc0, bc0));
            r1.y = silu_f(fmaf(acc[i][j][3], sc1, bc1));
            *(float2*)(base + p0 * 64 + ob)        = r0;
            *(float2*)(base + (p0 + 8) * 64 + ob)  = r1;
        }
    }
}

// ======================= K2a: 3x3 offset conv (64 -> 18) =======================
#define K2A_SMEM ((612 * 33 + 32 * 9 * 20) * 4)
__global__ void __launch_bounds__(256) k2a_offconv(
    const float* __restrict__ off_w, const float* __restrict__ off_b)
{
    extern __shared__ float sm[];
    float* tile = sm;             // [(yy*34+xx)*33 + cL]  halo tile 18 x 34, 32 ch (pad 33)
    float* ws   = sm + 612 * 33;  // [(cL*9+k)*20 + oc]    oc padded to 20
    const int t  = threadIdx.x;
    const int bx = blockIdx.x << 5;
    const int by = blockIdx.y << 4;
    const int b  = blockIdx.z;

    const float* x1b = g_x1 + b * (HW * 64);

    const int lx = t & 15, ly = t >> 4;
    int spos[9];
    #pragma unroll
    for (int k = 0; k < 9; k++) {
        int ky = k / 3, kx = k - ky * 3;
        spos[k] = ((ly + ky) * 34 + (lx + kx)) * 33;
    }
    u64 acc0[9], acc1[9];
    #pragma unroll
    for (int j = 0; j < 9; j++) {
        u64 ib = pk2(off_b[2 * j], off_b[2 * j + 1]);
        acc0[j] = ib; acc1[j] = ib;
    }

    #pragma unroll 1
    for (int ch = 0; ch < 2; ch++) {
        for (int e4 = t; e4 < 612 * 8; e4 += 256) {
            int s = e4 >> 3, c4 = (e4 & 7) << 2;
            int yy = s / 34, xx = s - yy * 34;
            int gy = by + yy - 1, gx = bx + xx - 1;
            float4 v = make_float4(0.f, 0.f, 0.f, 0.f);
            if (gy >= 0 && gy < 128 && gx >= 0 && gx < 128)
                v = *(const float4*)(x1b + (gy * 128 + gx) * 64 + ch * 32 + c4);
            float* d = tile + s * 33 + c4;
            d[0] = v.x; d[1] = v.y; d[2] = v.z; d[3] = v.w;
        }
        for (int e = t; e < 18 * 288; e += 256) {
            int oc = e / 288, r = e - oc * 288;
            ws[r * 20 + oc] = off_w[oc * 576 + ch * 288 + r];
        }
        __syncthreads();

        for (int c = 0; c < 32; c++) {
            const float* wc = ws + c * 180;
            #pragma unroll
            for (int k = 0; k < 9; k++) {
                float v0 = tile[spos[k] + c];
                float v1 = tile[spos[k] + 16 * 33 + c];
                u64 p0 = pk2(v0, v0), p1 = pk2(v1, v1);
                const float* wr = wc + k * 20;
                ulonglong2 wa  = *(const ulonglong2*)(wr);
                ulonglong2 wb  = *(const ulonglong2*)(wr + 4);
                ulonglong2 wcv = *(const ulonglong2*)(wr + 8);
                ulonglong2 wd  = *(const ulonglong2*)(wr + 12);
                u64 we = *(const u64*)(wr + 16);
                u64 wv[9] = { wa.x, wa.y, wb.x, wb.y, wcv.x, wcv.y, wd.x, wd.y, we };
                #pragma unroll
                for (int j = 0; j < 9; j++) {
                    acc0[j] = f2fma(p0, wv[j], acc0[j]);
                    acc1[j] = f2fma(p1, wv[j], acc1[j]);
                }
            }
        }
        __syncthreads();
    }

    int p0 = (by + ly) * 128 + bx + lx;
    float* o0 = g_off + (b * HW + p0) * 18;
    float* o1 = o0 + 16 * 18;
    #pragma unroll
    for (int j = 0; j < 9; j++) {
        *(u64*)(o0 + 2 * j) = acc0[j];
        *(u64*)(o1 + 2 * j) = acc1[j];
    }
}

// ================ K2b: deformable bilinear sampling + depthwise =================
// warp handles 8 consecutive pixels; lane owns channel pair (2*lane, 2*lane+1)
// dw weights loaded ONCE per warp (amortized 8x vs 1 px/warp)
__global__ void __launch_bounds__(256) k2b_sample(const float* __restrict__ dw)
{
    const int b = blockIdx.y;
    const int wid = threadIdx.x >> 5, lane = threadIdx.x & 31;
    const int pbase = (blockIdx.x << 6) + (wid << 3);   // 8 warps * 8 px = 64 px per CTA
    const int c0 = lane << 1;

    u64 dwp[9];
    #pragma unroll
    for (int k = 0; k < 9; k++) dwp[k] = pk2(dw[c0 * 9 + k], dw[c0 * 9 + 9 + k]);

    const float* x1b = g_x1 + b * (HW * 64) + c0;

    #pragma unroll 1
    for (int q = 0; q < 8; q++) {
        const int p = pbase + q;
        const int y = p >> 7, x = p & 127;
        const float* offp = g_off + (b * HW + p) * 18;
        float offv = (lane < 18) ? offp[lane] : 0.f;

        u64 acc = 0ULL;
        #pragma unroll
        for (int k = 0; k < 9; k++) {
            float dy = __shfl_sync(0xffffffffu, offv, 2 * k);
            float dx = __shfl_sync(0xffffffffu, offv, 2 * k + 1);
            float py = (float)(y + k / 3 - 1) + dy;
            float px = (float)(x + (k % 3) - 1) + dx;
            float y0f = floorf(py), x0f = floorf(px);
            float wy = py - y0f, wx = px - x0f;
            int y0 = (int)y0f, x0 = (int)x0f;
            bool yv0 = (y0 >= 0) && (y0 < 128);
            bool yv1 = (y0 + 1 >= 0) && (y0 + 1 < 128);
            bool xv0 = (x0 >= 0) && (x0 < 128);
            bool xv1 = (x0 + 1 >= 0) && (x0 + 1 < 128);
            u64 v00 = 0ULL, v01 = 0ULL, v10 = 0ULL, v11 = 0ULL;
            if (yv0 && xv0) v00 = *(const u64*)(x1b + (y0 * 128 + x0) * 64);
            if (yv0 && xv1) v01 = *(const u64*)(x1b + (y0 * 128 + x0 + 1) * 64);
            if (yv1 && xv0) v10 = *(const u64*)(x1b + ((y0 + 1) * 128 + x0) * 64);
            if (yv1 && xv1) v11 = *(const u64*)(x1b + ((y0 + 1) * 128 + x0 + 1) * 64);
            float omy = 1.f - wy, omx = 1.f - wx;
            u64 s = f2mul(v11, pk2(wy * wx, wy * wx));
            s = f2fma(v10, pk2(wy * omx, wy * omx), s);
            s = f2fma(v01, pk2(omy * wx, omy * wx), s);
            s = f2fma(v00, pk2(omy * omx, omy * omx), s);
            acc = f2fma(s, dwp[k], acc);
        }
        *(u64*)(g_d + (b * HW + p) * 64 + c0) = acc;
    }
}

// ================== K4: final 1x1 GEMM over concat(d, x2) + SiLU (mma.sync) ==================
__global__ void __launch_bounds__(256) k4_mma(
    const float* __restrict__ w3, const float* __restrict__ s3, const float* __restrict__ b3,
    float* __restrict__ out)
{
    extern __shared__ char smem[];
    const int t = threadIdx.x, wid = t >> 5, lane = t & 31;
    const int g = lane >> 2, tg = lane & 3;
    const int wm = wid & 3, wn = wid >> 2;
    const int b = blockIdx.y, P = blockIdx.x << 7;

    const uint32_t sb  = smem_u32(smem);
    const uint32_t aHi = sb + SM_AHI + (wm * 32 + (lane & 15)) * TS + (lane >> 4) * 16;
    const uint32_t aLo = aHi + TILE_B;
    const uint32_t bHi = sb + SM_BHI + (wn * 64 + (lane & 7)) * TS + ((lane >> 3) & 1) * 16;
    const uint32_t bLo = bHi + TILE_B;

    float acc[2][8][4];
    #pragma unroll
    for (int i = 0; i < 2; i++)
        #pragma unroll
        for (int j = 0; j < 8; j++)
            #pragma unroll
            for (int q = 0; q < 4; q++) acc[i][j][q] = 0.f;

    #pragma unroll 1
    for (int s = 0; s < 2; s++) {
        const float* abase = (s ? g_x2 : g_d) + (b * HW + P) * 64;
        // A: NHWC rows direct (row = pixel, cols = 64 channels of this stage)
        for (int e = t; e < 2048; e += 256) {
            int r = e >> 4, c4 = (e & 15) << 2;
            float4 v = *(const float4*)(abase + r * 64 + c4);
            uint32_t h01, l01, h23, l23;
            split2(v.x, v.y, h01, l01);
            split2(v.z, v.w, h23, l23);
            int off = r * TS + c4 * 2;
            *(uint32_t*)(smem + SM_AHI + off)     = h01;
            *(uint32_t*)(smem + SM_AHI + off + 4) = h23;
            *(uint32_t*)(smem + SM_ALO + off)     = l01;
            *(uint32_t*)(smem + SM_ALO + off + 4) = l23;
        }
        // B: w3 rows K-major direct
        for (int e = t; e < 2048; e += 256) {
            int o = e >> 4, c4 = (e & 15) << 2;
            float4 v = *(const float4*)(w3 + o * 128 + s * 64 + c4);
            uint32_t h01, l01, h23, l23;
            split2(v.x, v.y, h01, l01);
            split2(v.z, v.w, h23, l23);
            int off = o * TS + c4 * 2;
            *(uint32_t*)(smem + SM_BHI + off)     = h01;
            *(uint32_t*)(smem + SM_BHI + off + 4) = h23;
            *(uint32_t*)(smem + SM_BLO + off)     = l01;
            *(uint32_t*)(smem + SM_BLO + off + 4) = l23;
        }
        __syncthreads();
        mma_stage_ldsm(aHi, aLo, bHi, bLo, acc);
        __syncthreads();
    }

    // Epilogue: out is NCHW [b][o][p]
    #pragma unroll
    for (int i = 0; i < 2; i++) {
        #pragma unroll
        for (int j = 0; j < 8; j++) {
            int o = wn * 64 + j * 8 + 2 * tg;
            float sc0 = s3[o], sc1 = s3[o + 1];
            float bc0 = b3[o], bc1 = b3[o + 1];
            int p0 = P + wm * 32 + i * 16 + g;
            float* d0 = out + (b * 128 + o) * HW;
            float* d1 = out + (b * 128 + o + 1) * HW;
            d0[p0]     = silu_f(fmaf(acc[i][j][0], sc0, bc0));
            d1[p0]     = silu_f(fmaf(acc[i][j][1], sc1, bc1));
            d0[p0 + 8] = silu_f(fmaf(acc[i][j][2], sc0, bc0));
            d1[p0 + 8] = silu_f(fmaf(acc[i][j][3], sc1, bc1));
        }
    }
}

extern "C" void kernel_launch(void* const* d_in, const int* in_sizes, int n_in,
                              void* d_out, int out_size) {
    const float* x     = (const float*)d_in[0];
    const float* w1    = (const float*)d_in[1];
    const float* s1    = (const float*)d_in[2];
    const float* b1    = (const float*)d_in[3];
    const float* w2    = (const float*)d_in[4];
    const float* s2    = (const float*)d_in[5];
    const float* b2    = (const float*)d_in[6];
    const float* w3    = (const float*)d_in[7];
    const float* s3    = (const float*)d_in[8];
    const float* b3    = (const float*)d_in[9];
    const float* off_w = (const float*)d_in[10];
    const float* off_b = (const float*)d_in[11];
    const float* dw    = (const float*)d_in[12];
    float* out = (float*)d_out;

    cudaFuncSetAttribute(k1_mma, cudaFuncAttributeMaxDynamicSharedMemorySize, SM_MMA_TOTAL);
    cudaFuncSetAttribute(k2a_offconv, cudaFuncAttributeMaxDynamicSharedMemorySize, K2A_SMEM);
    cudaFuncSetAttribute(k4_mma, cudaFuncAttributeMaxDynamicSharedMemorySize, SM_MMA_TOTAL);

    dim3 g1(HW / 128, BATCH);
    k1_mma<<<g1, 256, SM_MMA_TOTAL>>>(x, w1, s1, b1, w2, s2, b2);

    dim3 g2a(128 / 32, 128 / 16, BATCH);
    k2a_offconv<<<g2a, 256, K2A_SMEM>>>(off_w, off_b);

    dim3 g2b(HW / 64, BATCH);
    k2b_sample<<<g2b, 256>>>(dw);

    dim3 g4(HW / 128, BATCH);
    k4_mma<<<g4, 256, SM_MMA_TOTAL>>>(w3, s3, b3, out);
}

// round 11
// speedup vs baseline: 1.1129x; 1.1129x over previous
#include <cuda_runtime.h>
#include <cuda_bf16.h>
#include <cstdint>

#define BATCH 8
#define HW    16384
#define HID   64

// ---------------- scratch (static device memory; no allocations) ----------------
__device__ float g_x1[BATCH * HW * HID];   // NHWC: [b][p][c]
__device__ float g_x2[BATCH * HW * HID];   // NHWC
__device__ float g_off[BATCH * HW * 18];   // [b][p][18]
__device__ float g_d [BATCH * HW * HID];   // NHWC

typedef unsigned long long u64;

__device__ __forceinline__ u64 pk2(float lo, float hi) {
    u64 r; asm("mov.b64 %0, {%1,%2};" : "=l"(r) : "f"(lo), "f"(hi)); return r;
}
__device__ __forceinline__ u64 f2fma(u64 a, u64 b, u64 c) {
    u64 d; asm("fma.rn.f32x2 %0,%1,%2,%3;" : "=l"(d) : "l"(a), "l"(b), "l"(c)); return d;
}
__device__ __forceinline__ u64 f2mul(u64 a, u64 b) {
    u64 d; asm("mul.rn.f32x2 %0,%1,%2;" : "=l"(d) : "l"(a), "l"(b)); return d;
}
__device__ __forceinline__ float silu_f(float v) {
    return __fdividef(v, 1.0f + __expf(-v));
}

// ---------------- mma.sync + ldmatrix helpers (baseline PTX) ----------------
__device__ __forceinline__ uint32_t smem_u32(const void* p) {
    uint32_t a;
    asm("{ .reg .u64 t; cvta.to.shared.u64 t, %1; cvt.u32.u64 %0, t; }" : "=r"(a) : "l"(p));
    return a;
}
__device__ __forceinline__ uint32_t bf2(float lo, float hi) {
    uint32_t r; asm("cvt.rn.bf16x2.f32 %0, %1, %2;" : "=r"(r) : "f"(hi), "f"(lo)); return r;
}
// split-bf16 of a float pair -> hi-pair u32 and lo-pair u32 (residuals)
__device__ __forceinline__ void split2(float a, float b, uint32_t& h, uint32_t& l) {
    h = bf2(a, b);
    float hf_lo = __uint_as_float(h << 16);
    float hf_hi = __uint_as_float(h & 0xFFFF0000u);
    l = bf2(a - hf_lo, b - hf_hi);
}
__device__ __forceinline__ void mma_bf16(float* d, const uint32_t* a, const uint32_t* bb) {
    asm volatile(
        "mma.sync.aligned.m16n8k16.row.col.f32.bf16.bf16.f32 "
        "{%0,%1,%2,%3}, {%4,%5,%6,%7}, {%8,%9}, {%0,%1,%2,%3};"
        : "+f"(d[0]), "+f"(d[1]), "+f"(d[2]), "+f"(d[3])
        : "r"(a[0]), "r"(a[1]), "r"(a[2]), "r"(a[3]), "r"(bb[0]), "r"(bb[1]));
}
__device__ __forceinline__ void ldsm4(uint32_t* r, uint32_t a) {
    asm volatile("ldmatrix.sync.aligned.m8n8.x4.shared.b16 {%0,%1,%2,%3}, [%4];"
        : "=r"(r[0]), "=r"(r[1]), "=r"(r[2]), "=r"(r[3]) : "r"(a));
}
__device__ __forceinline__ void ldsm2(uint32_t* r, uint32_t a) {
    asm volatile("ldmatrix.sync.aligned.m8n8.x2.shared.b16 {%0,%1}, [%2];"
        : "=r"(r[0]), "=r"(r[1]) : "r"(a));
}

// smem tile geometry: 128 rows x 64 bf16 cols, row stride 144 bytes (72 bf16)
// -> every 8-lane ldmatrix phase walks banks with a shift of 4/row: conflict-free
#define TS      144
#define TILE_B  (128 * TS)          // 18432
#define SM_AHI  0
#define SM_ALO  (TILE_B)
#define SM_BHI  (2 * TILE_B)
#define SM_BLO  (3 * TILE_B)
#define SM_MMA_TOTAL (4 * TILE_B)   // 73728 bytes -> 2 CTAs/SM (smem-wise)

// GEMM core for one K=64 stage via ldmatrix fragments.
__device__ __forceinline__ void mma_stage_ldsm(
    uint32_t aHi, uint32_t aLo, uint32_t bHi, uint32_t bLo, float acc[2][8][4])
{
    #pragma unroll
    for (int kk = 0; kk < 4; kk++) {
        const uint32_t kb = kk * 32;
        uint32_t ah[2][4], al[2][4];
        ldsm4(ah[0], aHi + kb);
        ldsm4(ah[1], aHi + kb + 16 * TS);
        ldsm4(al[0], aLo + kb);
        ldsm4(al[1], aLo + kb + 16 * TS);
        #pragma unroll
        for (int j = 0; j < 8; j++) {
            uint32_t bh[2], bl[2];
            ldsm2(bh, bHi + kb + j * 8 * TS);
            ldsm2(bl, bLo + kb + j * 8 * TS);
            #pragma unroll
            for (int i = 0; i < 2; i++) {
                mma_bf16(acc[i][j], ah[i], bh);
                mma_bf16(acc[i][j], ah[i], bl);
                mma_bf16(acc[i][j], al[i], bh);
            }
        }
    }
}

// ======================= K1: fused dual 1x1 GEMM + SiLU (mma.sync) =======================
// D[p][o] = sum_c x[b][c][p] * Wcat[o][c];  o<64 -> x1 (s1,b1), o>=64 -> x2 (s2,b2)
__global__ void __launch_bounds__(256, 2) k1_mma(
    const float* __restrict__ x,
    const float* __restrict__ w1, const float* __restrict__ s1, const float* __restrict__ b1,
    const float* __restrict__ w2, const float* __restrict__ s2, const float* __restrict__ b2)
{
    extern __shared__ char smem[];
    const int t = threadIdx.x, wid = t >> 5, lane = t & 31;
    const int g = lane >> 2, tg = lane & 3;
    const int wm = wid & 3, wn = wid >> 2;
    const int b = blockIdx.y, P = blockIdx.x << 7;

    const uint32_t sb  = smem_u32(smem);
    const uint32_t aHi = sb + SM_AHI + (wm * 32 + (lane & 15)) * TS + (lane >> 4) * 16;
    const uint32_t aLo = aHi + TILE_B;
    const uint32_t bHi = sb + SM_BHI + (wn * 64 + (lane & 7)) * TS + ((lane >> 3) & 1) * 16;
    const uint32_t bLo = bHi + TILE_B;

    float acc[2][8][4];
    #pragma unroll
    for (int i = 0; i < 2; i++)
        #pragma unroll
        for (int j = 0; j < 8; j++)
            #pragma unroll
            for (int q = 0; q < 4; q++) acc[i][j][q] = 0.f;

    const float* xb = x + b * (128 * HW) + P;

    #pragma unroll 1
    for (int s = 0; s < 2; s++) {
        // A: transpose x[c][p] -> rows = pixels, cols = channels (stage s: c in [s*64, s*64+64))
        for (int e = t; e < 2048; e += 256) {
            int r = e & 127, c4 = (e >> 7) << 2;
            const float* src = xb + (s * 64 + c4) * HW + r;
            float v0 = src[0], v1 = src[HW], v2 = src[2 * HW], v3 = src[3 * HW];
            uint32_t h01, l01, h23, l23;
            split2(v0, v1, h01, l01);
            split2(v2, v3, h23, l23);
            int off = r * TS + c4 * 2;
            *(uint32_t*)(smem + SM_AHI + off)     = h01;
            *(uint32_t*)(smem + SM_AHI + off + 4) = h23;
            *(uint32_t*)(smem + SM_ALO + off)     = l01;
            *(uint32_t*)(smem + SM_ALO + off + 4) = l23;
        }
        // B: Wcat rows, K-major direct
        for (int e = t; e < 2048; e += 256) {
            int o = e >> 4, c4 = (e & 15) << 2;
            const float* src = (o < 64 ? w1 + o * 128 : w2 + (o - 64) * 128) + s * 64 + c4;
            float4 v = *(const float4*)src;
            uint32_t h01, l01, h23, l23;
            split2(v.x, v.y, h01, l01);
            split2(v.z, v.w, h23, l23);
            int off = o * TS + c4 * 2;
            *(uint32_t*)(smem + SM_BHI + off)     = h01;
            *(uint32_t*)(smem + SM_BHI + off + 4) = h23;
            *(uint32_t*)(smem + SM_BLO + off)     = l01;
            *(uint32_t*)(smem + SM_BLO + off + 4) = l23;
        }
        __syncthreads();
        mma_stage_ldsm(aHi, aLo, bHi, bLo, acc);
        __syncthreads();
    }

    // Epilogue: acc[i][j] is 16x8 frag at (row wm*32+i*16, col wn*64+j*8)
    #pragma unroll
    for (int i = 0; i < 2; i++) {
        #pragma unroll
        for (int j = 0; j < 8; j++) {
            int o = wn * 64 + j * 8 + 2 * tg;
            bool first = (o < 64);
            int ob = o & 63;
            const float* sv = first ? s1 : s2;
            const float* bv = first ? b1 : b2;
            float sc0 = sv[ob], sc1 = sv[ob + 1];
            float bc0 = bv[ob], bc1 = bv[ob + 1];
            float* base = (first ? g_x1 : g_x2) + (b * HW) * 64;
            int p0 = P + wm * 32 + i * 16 + g;
            float2 r0, r1;
            r0.x = silu_f(fmaf(acc[i][j][0], sc0, bc0));
            r0.y = silu_f(fmaf(acc[i][j][1], sc1, bc1));
            r1.x = silu_f(fmaf(acc[i][j][2], sc0, bc0));
            r1.y = silu_f(fmaf(acc[i][j][3], sc1, bc1));
            *(float2*)(base + p0 * 64 + ob)        = r0;
            *(float2*)(base + (p0 + 8) * 64 + ob)  = r1;
        }
    }
}

// ======================= K2a: 3x3 offset conv (64 -> 18) =======================
#define K2A_SMEM ((612 * 33 + 32 * 9 * 20) * 4)
__global__ void __launch_bounds__(256) k2a_offconv(
    const float* __restrict__ off_w, const float* __restrict__ off_b)
{
    extern __shared__ float sm[];
    float* tile = sm;             // [(yy*34+xx)*33 + cL]  halo tile 18 x 34, 32 ch (pad 33)
    float* ws   = sm + 612 * 33;  // [(cL*9+k)*20 + oc]    oc padded to 20
    const int t  = threadIdx.x;
    const int bx = blockIdx.x << 5;
    const int by = blockIdx.y << 4;
    const int b  = blockIdx.z;

    const float* x1b = g_x1 + b * (HW * 64);

    const int lx = t & 15, ly = t >> 4;
    int spos[9];
    #pragma unroll
    for (int k = 0; k < 9; k++) {
        int ky = k / 3, kx = k - ky * 3;
        spos[k] = ((ly + ky) * 34 + (lx + kx)) * 33;
    }
    u64 acc0[9], acc1[9];
    #pragma unroll
    for (int j = 0; j < 9; j++) {
        u64 ib = pk2(off_b[2 * j], off_b[2 * j + 1]);
        acc0[j] = ib; acc1[j] = ib;
    }

    #pragma unroll 1
    for (int ch = 0; ch < 2; ch++) {
        for (int e4 = t; e4 < 612 * 8; e4 += 256) {
            int s = e4 >> 3, c4 = (e4 & 7) << 2;
            int yy = s / 34, xx = s - yy * 34;
            int gy = by + yy - 1, gx = bx + xx - 1;
            float4 v = make_float4(0.f, 0.f, 0.f, 0.f);
            if (gy >= 0 && gy < 128 && gx >= 0 && gx < 128)
                v = *(const float4*)(x1b + (gy * 128 + gx) * 64 + ch * 32 + c4);
            float* d = tile + s * 33 + c4;
            d[0] = v.x; d[1] = v.y; d[2] = v.z; d[3] = v.w;
        }
        for (int e = t; e < 18 * 288; e += 256) {
            int oc = e / 288, r = e - oc * 288;
            ws[r * 20 + oc] = off_w[oc * 576 + ch * 288 + r];
        }
        __syncthreads();

        for (int c = 0; c < 32; c++) {
            const float* wc = ws + c * 180;
            #pragma unroll
            for (int k = 0; k < 9; k++) {
                float v0 = tile[spos[k] + c];
                float v1 = tile[spos[k] + 16 * 33 + c];
                u64 p0 = pk2(v0, v0), p1 = pk2(v1, v1);
                const float* wr = wc + k * 20;
                ulonglong2 wa  = *(const ulonglong2*)(wr);
                ulonglong2 wb  = *(const ulonglong2*)(wr + 4);
                ulonglong2 wcv = *(const ulonglong2*)(wr + 8);
                ulonglong2 wd  = *(const ulonglong2*)(wr + 12);
                u64 we = *(const u64*)(wr + 16);
                u64 wv[9] = { wa.x, wa.y, wb.x, wb.y, wcv.x, wcv.y, wd.x, wd.y, we };
                #pragma unroll
                for (int j = 0; j < 9; j++) {
                    acc0[j] = f2fma(p0, wv[j], acc0[j]);
                    acc1[j] = f2fma(p1, wv[j], acc1[j]);
                }
            }
        }
        __syncthreads();
    }

    int p0 = (by + ly) * 128 + bx + lx;
    float* o0 = g_off + (b * HW + p0) * 18;
    float* o1 = o0 + 16 * 18;
    #pragma unroll
    for (int j = 0; j < 9; j++) {
        *(u64*)(o0 + 2 * j) = acc0[j];
        *(u64*)(o1 + 2 * j) = acc1[j];
    }
}

// ================ K2b: deformable bilinear sampling + depthwise =================
// warp handles 8 consecutive pixels; lane owns channel pair (2*lane, 2*lane+1)
__global__ void __launch_bounds__(256) k2b_sample(const float* __restrict__ dw)
{
    const int b = blockIdx.y;
    const int wid = threadIdx.x >> 5, lane = threadIdx.x & 31;
    const int pbase = (blockIdx.x << 6) + (wid << 3);   // 8 warps * 8 px = 64 px per CTA
    const int c0 = lane << 1;

    u64 dwp[9];
    #pragma unroll
    for (int k = 0; k < 9; k++) dwp[k] = pk2(dw[c0 * 9 + k], dw[c0 * 9 + 9 + k]);

    const float* x1b = g_x1 + b * (HW * 64) + c0;

    #pragma unroll 1
    for (int q = 0; q < 8; q++) {
        const int p = pbase + q;
        const int y = p >> 7, x = p & 127;
        const float* offp = g_off + (b * HW + p) * 18;
        float offv = (lane < 18) ? offp[lane] : 0.f;

        u64 acc = 0ULL;
        #pragma unroll
        for (int k = 0; k < 9; k++) {
            float dy = __shfl_sync(0xffffffffu, offv, 2 * k);
            float dx = __shfl_sync(0xffffffffu, offv, 2 * k + 1);
            float py = (float)(y + k / 3 - 1) + dy;
            float px = (float)(x + (k % 3) - 1) + dx;
            float y0f = floorf(py), x0f = floorf(px);
            float wy = py - y0f, wx = px - x0f;
            int y0 = (int)y0f, x0 = (int)x0f;
            bool yv0 = (y0 >= 0) && (y0 < 128);
            bool yv1 = (y0 + 1 >= 0) && (y0 + 1 < 128);
            bool xv0 = (x0 >= 0) && (x0 < 128);
            bool xv1 = (x0 + 1 >= 0) && (x0 + 1 < 128);
            u64 v00 = 0ULL, v01 = 0ULL, v10 = 0ULL, v11 = 0ULL;
            if (yv0 && xv0) v00 = *(const u64*)(x1b + (y0 * 128 + x0) * 64);
            if (yv0 && xv1) v01 = *(const u64*)(x1b + (y0 * 128 + x0 + 1) * 64);
            if (yv1 && xv0) v10 = *(const u64*)(x1b + ((y0 + 1) * 128 + x0) * 64);
            if (yv1 && xv1) v11 = *(const u64*)(x1b + ((y0 + 1) * 128 + x0 + 1) * 64);
            float omy = 1.f - wy, omx = 1.f - wx;
            u64 s = f2mul(v11, pk2(wy * wx, wy * wx));
            s = f2fma(v10, pk2(wy * omx, wy * omx), s);
            s = f2fma(v01, pk2(omy * wx, omy * wx), s);
            s = f2fma(v00, pk2(omy * omx, omy * omx), s);
            acc = f2fma(s, dwp[k], acc);
        }
        *(u64*)(g_d + (b * HW + p) * 64 + c0) = acc;
    }
}

// ================== K4: final 1x1 GEMM over concat(d, x2) + SiLU (mma.sync) ==================
__global__ void __launch_bounds__(256, 2) k4_mma(
    const float* __restrict__ w3, const float* __restrict__ s3, const float* __restrict__ b3,
    float* __restrict__ out)
{
    extern __shared__ char smem[];
    const int t = threadIdx.x, wid = t >> 5, lane = t & 31;
    const int g = lane >> 2, tg = lane & 3;
    const int wm = wid & 3, wn = wid >> 2;
    const int b = blockIdx.y, P = blockIdx.x << 7;

    const uint32_t sb  = smem_u32(smem);
    const uint32_t aHi = sb + SM_AHI + (wm * 32 + (lane & 15)) * TS + (lane >> 4) * 16;
    const uint32_t aLo = aHi + TILE_B;
    const uint32_t bHi = sb + SM_BHI + (wn * 64 + (lane & 7)) * TS + ((lane >> 3) & 1) * 16;
    const uint32_t bLo = bHi + TILE_B;

    float acc[2][8][4];
    #pragma unroll
    for (int i = 0; i < 2; i++)
        #pragma unroll
        for (int j = 0; j < 8; j++)
            #pragma unroll
            for (int q = 0; q < 4; q++) acc[i][j][q] = 0.f;

    #pragma unroll 1
    for (int s = 0; s < 2; s++) {
        const float* abase = (s ? g_x2 : g_d) + (b * HW + P) * 64;
        // A: NHWC rows direct (row = pixel, cols = 64 channels of this stage)
        for (int e = t; e < 2048; e += 256) {
            int r = e >> 4, c4 = (e & 15) << 2;
            float4 v = *(const float4*)(abase + r * 64 + c4);
            uint32_t h01, l01, h23, l23;
            split2(v.x, v.y, h01, l01);
            split2(v.z, v.w, h23, l23);
            int off = r * TS + c4 * 2;
            *(uint32_t*)(smem + SM_AHI + off)     = h01;
            *(uint32_t*)(smem + SM_AHI + off + 4) = h23;
            *(uint32_t*)(smem + SM_ALO + off)     = l01;
            *(uint32_t*)(smem + SM_ALO + off + 4) = l23;
        }
        // B: w3 rows K-major direct
        for (int e = t; e < 2048; e += 256) {
            int o = e >> 4, c4 = (e & 15) << 2;
            float4 v = *(const float4*)(w3 + o * 128 + s * 64 + c4);
            uint32_t h01, l01, h23, l23;
            split2(v.x, v.y, h01, l01);
            split2(v.z, v.w, h23, l23);
            int off = o * TS + c4 * 2;
            *(uint32_t*)(smem + SM_BHI + off)     = h01;
            *(uint32_t*)(smem + SM_BHI + off + 4) = h23;
            *(uint32_t*)(smem + SM_BLO + off)     = l01;
            *(uint32_t*)(smem + SM_BLO + off + 4) = l23;
        }
        __syncthreads();
        mma_stage_ldsm(aHi, aLo, bHi, bLo, acc);
        __syncthreads();
    }

    // Epilogue: out is NCHW [b][o][p]
    #pragma unroll
    for (int i = 0; i < 2; i++) {
        #pragma unroll
        for (int j = 0; j < 8; j++) {
            int o = wn * 64 + j * 8 + 2 * tg;
            float sc0 = s3[o], sc1 = s3[o + 1];
            float bc0 = b3[o], bc1 = b3[o + 1];
            int p0 = P + wm * 32 + i * 16 + g;
            float* d0 = out + (b * 128 + o) * HW;
            float* d1 = out + (b * 128 + o + 1) * HW;
            d0[p0]     = silu_f(fmaf(acc[i][j][0], sc0, bc0));
            d1[p0]     = silu_f(fmaf(acc[i][j][1], sc1, bc1));
            d0[p0 + 8] = silu_f(fmaf(acc[i][j][2], sc0, bc0));
            d1[p0 + 8] = silu_f(fmaf(acc[i][j][3], sc1, bc1));
        }
    }
}

extern "C" void kernel_launch(void* const* d_in, const int* in_sizes, int n_in,
                              void* d_out, int out_size) {
    const float* x     = (const float*)d_in[0];
    const float* w1    = (const float*)d_in[1];
    const float* s1    = (const float*)d_in[2];
    const float* b1    = (const float*)d_in[3];
    const float* w2    = (const float*)d_in[4];
    const float* s2    = (const float*)d_in[5];
    const float* b2    = (const float*)d_in[6];
    const float* w3    = (const float*)d_in[7];
    const float* s3    = (const float*)d_in[8];
    const float* b3    = (const float*)d_in[9];
    const float* off_w = (const float*)d_in[10];
    const float* off_b = (const float*)d_in[11];
    const float* dw    = (const float*)d_in[12];
    float* out = (float*)d_out;

    cudaFuncSetAttribute(k1_mma, cudaFuncAttributeMaxDynamicSharedMemorySize, SM_MMA_TOTAL);
    cudaFuncSetAttribute(k2a_offconv, cudaFuncAttributeMaxDynamicSharedMemorySize, K2A_SMEM);
    cudaFuncSetAttribute(k4_mma, cudaFuncAttributeMaxDynamicSharedMemorySize, SM_MMA_TOTAL);

    dim3 g1(HW / 128, BATCH);
    k1_mma<<<g1, 256, SM_MMA_TOTAL>>>(x, w1, s1, b1, w2, s2, b2);

    dim3 g2a(128 / 32, 128 / 16, BATCH);
    k2a_offconv<<<g2a, 256, K2A_SMEM>>>(off_w, off_b);

    dim3 g2b(HW / 64, BATCH);
    k2b_sample<<<g2b, 256>>>(dw);

    dim3 g4(HW / 128, BATCH);
    k4_mma<<<g4, 256, SM_MMA_TOTAL>>>(w3, s3, b3, out);
}

// round 12
// speedup vs baseline: 1.1503x; 1.0336x over previous
#include <cuda_runtime.h>
#include <cuda_bf16.h>
#include <cstdint>

#define BATCH 8
#define HW    16384
#define HID   64

// ---------------- scratch (static device memory; no allocations) ----------------
__device__ float g_x1[BATCH * HW * HID];   // NHWC: [b][p][c]
__device__ float g_x2[BATCH * HW * HID];   // NHWC
__device__ float g_off[BATCH * HW * 18];   // [b][p][18]
__device__ float g_d [BATCH * HW * HID];   // NHWC

typedef unsigned long long u64;

__device__ __forceinline__ u64 pk2(float lo, float hi) {
    u64 r; asm("mov.b64 %0, {%1,%2};" : "=l"(r) : "f"(lo), "f"(hi)); return r;
}
__device__ __forceinline__ u64 f2fma(u64 a, u64 b, u64 c) {
    u64 d; asm("fma.rn.f32x2 %0,%1,%2,%3;" : "=l"(d) : "l"(a), "l"(b), "l"(c)); return d;
}
__device__ __forceinline__ u64 f2mul(u64 a, u64 b) {
    u64 d; asm("mul.rn.f32x2 %0,%1,%2;" : "=l"(d) : "l"(a), "l"(b)); return d;
}
__device__ __forceinline__ float silu_f(float v) {
    return __fdividef(v, 1.0f + __expf(-v));
}

// ---------------- mma.sync helpers (baseline PTX; works on compute_103) ----------------
__device__ __forceinline__ uint32_t bf2(float lo, float hi) {
    uint32_t r; asm("cvt.rn.bf16x2.f32 %0, %1, %2;" : "=r"(r) : "f"(hi), "f"(lo)); return r;
}
// split-bf16 of a float pair -> hi-pair u32 and lo-pair u32 (residuals)
__device__ __forceinline__ void split2(float a, float b, uint32_t& h, uint32_t& l) {
    h = bf2(a, b);
    float hf_lo = __uint_as_float(h << 16);
    float hf_hi = __uint_as_float(h & 0xFFFF0000u);
    l = bf2(a - hf_lo, b - hf_hi);
}
__device__ __forceinline__ void mma_bf16(float* d, uint32_t a0, uint32_t a1, uint32_t a2, uint32_t a3,
                                         uint32_t b0, uint32_t b1) {
    asm volatile(
        "mma.sync.aligned.m16n8k16.row.col.f32.bf16.bf16.f32 "
        "{%0,%1,%2,%3}, {%4,%5,%6,%7}, {%8,%9}, {%0,%1,%2,%3};"
        : "+f"(d[0]), "+f"(d[1]), "+f"(d[2]), "+f"(d[3])
        : "r"(a0), "r"(a1), "r"(a2), "r"(a3), "r"(b0), "r"(b1));
}

// smem tile geometry: 128 rows x 64 bf16 cols, row stride 144 bytes (72 bf16)
#define TS      144
#define TILE_B  (128 * TS)          // 18432
#define SM_AHI  0
#define SM_ALO  (TILE_B)
#define SM_BHI  (2 * TILE_B)
#define SM_BLO  (3 * TILE_B)
#define SM_MMA_TOTAL (4 * TILE_B)   // 73728 bytes -> 2 CTAs/SM

// GEMM core (round-8 scheme): scalar LDS.32 fragment loads, 3-term split-bf16.
// Warp wm (0..3) owns rows wm*32..+31; warp wn (0..1) owns cols wn*64..+63.
__device__ __forceinline__ void mma_stage_compute(
    const char* smem, int wm, int wn, int g, int tg, float acc[2][8][4])
{
    #pragma unroll
    for (int kk = 0; kk < 4; kk++) {
        const int kb = kk * 32 + tg * 4;  // byte offset of k-pair (2tg) within 64-col tile
        uint32_t ah[2][4], al[2][4];
        #pragma unroll
        for (int i = 0; i < 2; i++) {
            int r0 = (wm * 32 + i * 16 + g) * TS + kb;
            int r1 = r0 + 8 * TS;
            ah[i][0] = *(const uint32_t*)(smem + SM_AHI + r0);
            ah[i][1] = *(const uint32_t*)(smem + SM_AHI + r1);
            ah[i][2] = *(const uint32_t*)(smem + SM_AHI + r0 + 16);
            ah[i][3] = *(const uint32_t*)(smem + SM_AHI + r1 + 16);
            al[i][0] = *(const uint32_t*)(smem + SM_ALO + r0);
            al[i][1] = *(const uint32_t*)(smem + SM_ALO + r1);
            al[i][2] = *(const uint32_t*)(smem + SM_ALO + r0 + 16);
            al[i][3] = *(const uint32_t*)(smem + SM_ALO + r1 + 16);
        }
        #pragma unroll
        for (int j = 0; j < 8; j++) {
            int rb = (wn * 64 + j * 8 + g) * TS + kb;
            uint32_t bh0 = *(const uint32_t*)(smem + SM_BHI + rb);
            uint32_t bh1 = *(const uint32_t*)(smem + SM_BHI + rb + 16);
            uint32_t bl0 = *(const uint32_t*)(smem + SM_BLO + rb);
            uint32_t bl1 = *(const uint32_t*)(smem + SM_BLO + rb + 16);
            #pragma unroll
            for (int i = 0; i < 2; i++) {
                mma_bf16(acc[i][j], ah[i][0], ah[i][1], ah[i][2], ah[i][3], bh0, bh1);
                mma_bf16(acc[i][j], ah[i][0], ah[i][1], ah[i][2], ah[i][3], bl0, bl1);
                mma_bf16(acc[i][j], al[i][0], al[i][1], al[i][2], al[i][3], bh0, bh1);
            }
        }
    }
}

// ======================= K1: fused dual 1x1 GEMM + SiLU (mma.sync) =======================
// D[p][o] = sum_c x[b][c][p] * Wcat[o][c];  o<64 -> x1 (s1,b1), o>=64 -> x2 (s2,b2)
__global__ void __launch_bounds__(256, 2) k1_mma(
    const float* __restrict__ x,
    const float* __restrict__ w1, const float* __restrict__ s1, const float* __restrict__ b1,
    const float* __restrict__ w2, const float* __restrict__ s2, const float* __restrict__ b2)
{
    extern __shared__ char smem[];
    const int t = threadIdx.x, wid = t >> 5, lane = t & 31;
    const int g = lane >> 2, tg = lane & 3;
    const int wm = wid & 3, wn = wid >> 2;
    const int b = blockIdx.y, P = blockIdx.x << 7;

    float acc[2][8][4];
    #pragma unroll
    for (int i = 0; i < 2; i++)
        #pragma unroll
        for (int j = 0; j < 8; j++)
            #pragma unroll
            for (int q = 0; q < 4; q++) acc[i][j][q] = 0.f;

    const float* xb = x + b * (128 * HW) + P;

    #pragma unroll 1
    for (int s = 0; s < 2; s++) {
        // A: transpose x[c][p] -> rows = pixels, cols = channels (stage s: c in [s*64, s*64+64))
        for (int e = t; e < 2048; e += 256) {
            int r = e & 127, c4 = (e >> 7) << 2;
            const float* src = xb + (s * 64 + c4) * HW + r;
            float v0 = src[0], v1 = src[HW], v2 = src[2 * HW], v3 = src[3 * HW];
            uint32_t h01, l01, h23, l23;
            split2(v0, v1, h01, l01);
            split2(v2, v3, h23, l23);
            int off = r * TS + c4 * 2;
            *(uint32_t*)(smem + SM_AHI + off)     = h01;
            *(uint32_t*)(smem + SM_AHI + off + 4) = h23;
            *(uint32_t*)(smem + SM_ALO + off)     = l01;
            *(uint32_t*)(smem + SM_ALO + off + 4) = l23;
        }
        // B: Wcat rows, K-major direct
        for (int e = t; e < 2048; e += 256) {
            int o = e >> 4, c4 = (e & 15) << 2;
            const float* src = (o < 64 ? w1 + o * 128 : w2 + (o - 64) * 128) + s * 64 + c4;
            float4 v = *(const float4*)src;
            uint32_t h01, l01, h23, l23;
            split2(v.x, v.y, h01, l01);
            split2(v.z, v.w, h23, l23);
            int off = o * TS + c4 * 2;
            *(uint32_t*)(smem + SM_BHI + off)     = h01;
            *(uint32_t*)(smem + SM_BHI + off + 4) = h23;
            *(uint32_t*)(smem + SM_BLO + off)     = l01;
            *(uint32_t*)(smem + SM_BLO + off + 4) = l23;
        }
        __syncthreads();
        mma_stage_compute(smem, wm, wn, g, tg, acc);
        __syncthreads();
    }

    // Epilogue: acc[i][j] is 16x8 frag at (row wm*32+i*16, col wn*64+j*8)
    #pragma unroll
    for (int i = 0; i < 2; i++) {
        #pragma unroll
        for (int j = 0; j < 8; j++) {
            int o = wn * 64 + j * 8 + 2 * tg;
            bool first = (o < 64);
            int ob = o & 63;
            const float* sv = first ? s1 : s2;
            const float* bv = first ? b1 : b2;
            float sc0 = sv[ob], sc1 = sv[ob + 1];
            float bc0 = bv[ob], bc1 = bv[ob + 1];
            float* base = (first ? g_x1 : g_x2) + (b * HW) * 64;
            int p0 = P + wm * 32 + i * 16 + g;
            float2 r0, r1;
            r0.x = silu_f(fmaf(acc[i][j][0], sc0, bc0));
            r0.y = silu_f(fmaf(acc[i][j][1], sc1, bc1));
            r1.x = silu_f(fmaf(acc[i][j][2], sc0, bc0));
            r1.y = silu_f(fmaf(acc[i][j][3], sc1, bc1));
            *(float2*)(base + p0 * 64 + ob)        = r0;
            *(float2*)(base + (p0 + 8) * 64 + ob)  = r1;
        }
    }
}

// ======================= K2a: 3x3 offset conv (64 -> 18) =======================
#define K2A_SMEM ((612 * 33 + 32 * 9 * 20) * 4)
__global__ void __launch_bounds__(256) k2a_offconv(
    const float* __restrict__ off_w, const float* __restrict__ off_b)
{
    extern __shared__ float sm[];
    float* tile = sm;             // [(yy*34+xx)*33 + cL]  halo tile 18 x 34, 32 ch (pad 33)
    float* ws   = sm + 612 * 33;  // [(cL*9+k)*20 + oc]    oc padded to 20
    const int t  = threadIdx.x;
    const int bx = blockIdx.x << 5;
    const int by = blockIdx.y << 4;
    const int b  = blockIdx.z;

    const float* x1b = g_x1 + b * (HW * 64);

    const int lx = t & 15, ly = t >> 4;
    int spos[9];
    #pragma unroll
    for (int k = 0; k < 9; k++) {
        int ky = k / 3, kx = k - ky * 3;
        spos[k] = ((ly + ky) * 34 + (lx + kx)) * 33;
    }
    u64 acc0[9], acc1[9];
    #pragma unroll
    for (int j = 0; j < 9; j++) {
        u64 ib = pk2(off_b[2 * j], off_b[2 * j + 1]);
        acc0[j] = ib; acc1[j] = ib;
    }

    #pragma unroll 1
    for (int ch = 0; ch < 2; ch++) {
        for (int e4 = t; e4 < 612 * 8; e4 += 256) {
            int s = e4 >> 3, c4 = (e4 & 7) << 2;
            int yy = s / 34, xx = s - yy * 34;
            int gy = by + yy - 1, gx = bx + xx - 1;
            float4 v = make_float4(0.f, 0.f, 0.f, 0.f);
            if (gy >= 0 && gy < 128 && gx >= 0 && gx < 128)
                v = *(const float4*)(x1b + (gy * 128 + gx) * 64 + ch * 32 + c4);
            float* d = tile + s * 33 + c4;
            d[0] = v.x; d[1] = v.y; d[2] = v.z; d[3] = v.w;
        }
        for (int e = t; e < 18 * 288; e += 256) {
            int oc = e / 288, r = e - oc * 288;
            ws[r * 20 + oc] = off_w[oc * 576 + ch * 288 + r];
        }
        __syncthreads();

        for (int c = 0; c < 32; c++) {
            const float* wc = ws + c * 180;
            #pragma unroll
            for (int k = 0; k < 9; k++) {
                float v0 = tile[spos[k] + c];
                float v1 = tile[spos[k] + 16 * 33 + c];
                u64 p0 = pk2(v0, v0), p1 = pk2(v1, v1);
                const float* wr = wc + k * 20;
                ulonglong2 wa  = *(const ulonglong2*)(wr);
                ulonglong2 wb  = *(const ulonglong2*)(wr + 4);
                ulonglong2 wcv = *(const ulonglong2*)(wr + 8);
                ulonglong2 wd  = *(const ulonglong2*)(wr + 12);
                u64 we = *(const u64*)(wr + 16);
                u64 wv[9] = { wa.x, wa.y, wb.x, wb.y, wcv.x, wcv.y, wd.x, wd.y, we };
                #pragma unroll
                for (int j = 0; j < 9; j++) {
                    acc0[j] = f2fma(p0, wv[j], acc0[j]);
                    acc1[j] = f2fma(p1, wv[j], acc1[j]);
                }
            }
        }
        __syncthreads();
    }

    int p0 = (by + ly) * 128 + bx + lx;
    float* o0 = g_off + (b * HW + p0) * 18;
    float* o1 = o0 + 16 * 18;
    #pragma unroll
    for (int j = 0; j < 9; j++) {
        *(u64*)(o0 + 2 * j) = acc0[j];
        *(u64*)(o1 + 2 * j) = acc1[j];
    }
}

// ================ K2b: deformable bilinear sampling + depthwise =================
// warp handles 8 consecutive pixels; lane owns channel pair (2*lane, 2*lane+1)
__global__ void __launch_bounds__(256) k2b_sample(const float* __restrict__ dw)
{
    const int b = blockIdx.y;
    const int wid = threadIdx.x >> 5, lane = threadIdx.x & 31;
    const int pbase = (blockIdx.x << 6) + (wid << 3);   // 8 warps * 8 px = 64 px per CTA
    const int c0 = lane << 1;

    u64 dwp[9];
    #pragma unroll
    for (int k = 0; k < 9; k++) dwp[k] = pk2(dw[c0 * 9 + k], dw[c0 * 9 + 9 + k]);

    const float* x1b = g_x1 + b * (HW * 64) + c0;

    #pragma unroll 1
    for (int q = 0; q < 8; q++) {
        const int p = pbase + q;
        const int y = p >> 7, x = p & 127;
        const float* offp = g_off + (b * HW + p) * 18;
        float offv = (lane < 18) ? offp[lane] : 0.f;

        u64 acc = 0ULL;
        #pragma unroll
        for (int k = 0; k < 9; k++) {
            float dy = __shfl_sync(0xffffffffu, offv, 2 * k);
            float dx = __shfl_sync(0xffffffffu, offv, 2 * k + 1);
            float py = (float)(y + k / 3 - 1) + dy;
            float px = (float)(x + (k % 3) - 1) + dx;
            float y0f = floorf(py), x0f = floorf(px);
            float wy = py - y0f, wx = px - x0f;
            int y0 = (int)y0f, x0 = (int)x0f;
            bool yv0 = (y0 >= 0) && (y0 < 128);
            bool yv1 = (y0 + 1 >= 0) && (y0 + 1 < 128);
            bool xv0 = (x0 >= 0) && (x0 < 128);
            bool xv1 = (x0 + 1 >= 0) && (x0 + 1 < 128);
            u64 v00 = 0ULL, v01 = 0ULL, v10 = 0ULL, v11 = 0ULL;
            if (yv0 && xv0) v00 = *(const u64*)(x1b + (y0 * 128 + x0) * 64);
            if (yv0 && xv1) v01 = *(const u64*)(x1b + (y0 * 128 + x0 + 1) * 64);
            if (yv1 && xv0) v10 = *(const u64*)(x1b + ((y0 + 1) * 128 + x0) * 64);
            if (yv1 && xv1) v11 = *(const u64*)(x1b + ((y0 + 1) * 128 + x0 + 1) * 64);
            float omy = 1.f - wy, omx = 1.f - wx;
            u64 s = f2mul(v11, pk2(wy * wx, wy * wx));
            s = f2fma(v10, pk2(wy * omx, wy * omx), s);
            s = f2fma(v01, pk2(omy * wx, omy * wx), s);
            s = f2fma(v00, pk2(omy * omx, omy * omx), s);
            acc = f2fma(s, dwp[k], acc);
        }
        *(u64*)(g_d + (b * HW + p) * 64 + c0) = acc;
    }
}

// ================== K4: final 1x1 GEMM over concat(d, x2) + SiLU (mma.sync) ==================
__global__ void __launch_bounds__(256, 2) k4_mma(
    const float* __restrict__ w3, const float* __restrict__ s3, const float* __restrict__ b3,
    float* __restrict__ out)
{
    extern __shared__ char smem[];
    const int t = threadIdx.x, wid = t >> 5, lane = t & 31;
    const int g = lane >> 2, tg = lane & 3;
    const int wm = wid & 3, wn = wid >> 2;
    const int b = blockIdx.y, P = blockIdx.x << 7;

    float acc[2][8][4];
    #pragma unroll
    for (int i = 0; i < 2; i++)
        #pragma unroll
        for (int j = 0; j < 8; j++)
            #pragma unroll
            for (int q = 0; q < 4; q++) acc[i][j][q] = 0.f;

    #pragma unroll 1
    for (int s = 0; s < 2; s++) {
        const float* abase = (s ? g_x2 : g_d) + (b * HW + P) * 64;
        // A: NHWC rows direct (row = pixel, cols = 64 channels of this stage)
        for (int e = t; e < 2048; e += 256) {
            int r = e >> 4, c4 = (e & 15) << 2;
            float4 v = *(const float4*)(abase + r * 64 + c4);
            uint32_t h01, l01, h23, l23;
            split2(v.x, v.y, h01, l01);
            split2(v.z, v.w, h23, l23);
            int off = r * TS + c4 * 2;
            *(uint32_t*)(smem + SM_AHI + off)     = h01;
            *(uint32_t*)(smem + SM_AHI + off + 4) = h23;
            *(uint32_t*)(smem + SM_ALO + off)     = l01;
            *(uint32_t*)(smem + SM_ALO + off + 4) = l23;
        }
        // B: w3 rows K-major direct
        for (int e = t; e < 2048; e += 256) {
            int o = e >> 4, c4 = (e & 15) << 2;
            float4 v = *(const float4*)(w3 + o * 128 + s * 64 + c4);
            uint32_t h01, l01, h23, l23;
            split2(v.x, v.y, h01, l01);
            split2(v.z, v.w, h23, l23);
            int off = o * TS + c4 * 2;
            *(uint32_t*)(smem + SM_BHI + off)     = h01;
            *(uint32_t*)(smem + SM_BHI + off + 4) = h23;
            *(uint32_t*)(smem + SM_BLO + off)     = l01;
            *(uint32_t*)(smem + SM_BLO + off + 4) = l23;
        }
        __syncthreads();
        mma_stage_compute(smem, wm, wn, g, tg, acc);
        __syncthreads();
    }

    // Epilogue: out is NCHW [b][o][p]
    #pragma unroll
    for (int i = 0; i < 2; i++) {
        #pragma unroll
        for (int j = 0; j < 8; j++) {
            int o = wn * 64 + j * 8 + 2 * tg;
            float sc0 = s3[o], sc1 = s3[o + 1];
            float bc0 = b3[o], bc1 = b3[o + 1];
            int p0 = P + wm * 32 + i * 16 + g;
            float* d0 = out + (b * 128 + o) * HW;
            float* d1 = out + (b * 128 + o + 1) * HW;
            d0[p0]     = silu_f(fmaf(acc[i][j][0], sc0, bc0));
            d1[p0]     = silu_f(fmaf(acc[i][j][1], sc1, bc1));
            d0[p0 + 8] = silu_f(fmaf(acc[i][j][2], sc0, bc0));
            d1[p0 + 8] = silu_f(fmaf(acc[i][j][3], sc1, bc1));
        }
    }
}

extern "C" void kernel_launch(void* const* d_in, const int* in_sizes, int n_in,
                              void* d_out, int out_size) {
    const float* x     = (const float*)d_in[0];
    const float* w1    = (const float*)d_in[1];
    const float* s1    = (const float*)d_in[2];
    const float* b1    = (const float*)d_in[3];
    const float* w2    = (const float*)d_in[4];
    const float* s2    = (const float*)d_in[5];
    const float* b2    = (const float*)d_in[6];
    const float* w3    = (const float*)d_in[7];
    const float* s3    = (const float*)d_in[8];
    const float* b3    = (const float*)d_in[9];
    const float* off_w = (const float*)d_in[10];
    const float* off_b = (const float*)d_in[11];
    const float* dw    = (const float*)d_in[12];
    float* out = (float*)d_out;

    cudaFuncSetAttribute(k1_mma, cudaFuncAttributeMaxDynamicSharedMemorySize, SM_MMA_TOTAL);
    cudaFuncSetAttribute(k2a_offconv, cudaFuncAttributeMaxDynamicSharedMemorySize, K2A_SMEM);
    cudaFuncSetAttribute(k4_mma, cudaFuncAttributeMaxDynamicSharedMemorySize, SM_MMA_TOTAL);

    dim3 g1(HW / 128, BATCH);
    k1_mma<<<g1, 256, SM_MMA_TOTAL>>>(x, w1, s1, b1, w2, s2, b2);

    dim3 g2a(128 / 32, 128 / 16, BATCH);
    k2a_offconv<<<g2a, 256, K2A_SMEM>>>(off_w, off_b);

    dim3 g2b(HW / 64, BATCH);
    k2b_sample<<<g2b, 256>>>(dw);

    dim3 g4(HW / 128, BATCH);
    k4_mma<<<g4, 256, SM_MMA_TOTAL>>>(w3, s3, b3, out);
}

// round 13
// speedup vs baseline: 1.2378x; 1.0760x over previous
#include <cuda_runtime.h>
#include <cuda_bf16.h>
#include <cuda_fp16.h>
#include <cstdint>

#define BATCH 8
#define HW    16384
#define HID   64

// ---------------- scratch (static device memory; no allocations) ----------------
__device__ float g_x1[BATCH * HW * HID];   // NHWC: [b][p][c]
__device__ float g_x2[BATCH * HW * HID];   // NHWC
__device__ float g_off[BATCH * HW * 18];   // [b][p][18]
__device__ float g_d [BATCH * HW * HID];   // NHWC

typedef unsigned long long u64;

__device__ __forceinline__ u64 pk2(float lo, float hi) {
    u64 r; asm("mov.b64 %0, {%1,%2};" : "=l"(r) : "f"(lo), "f"(hi)); return r;
}
__device__ __forceinline__ u64 f2fma(u64 a, u64 b, u64 c) {
    u64 d; asm("fma.rn.f32x2 %0,%1,%2,%3;" : "=l"(d) : "l"(a), "l"(b), "l"(c)); return d;
}
__device__ __forceinline__ u64 f2mul(u64 a, u64 b) {
    u64 d; asm("mul.rn.f32x2 %0,%1,%2;" : "=l"(d) : "l"(a), "l"(b)); return d;
}
__device__ __forceinline__ float silu_f(float v) {
    return __fdividef(v, 1.0f + __expf(-v));
}

// ---------------- mma.sync helpers (baseline PTX; works on compute_103) ----------------
// fp16x2 pack: lo -> low half, hi -> high half
__device__ __forceinline__ uint32_t h2pk(float lo, float hi) {
    uint32_t r; asm("cvt.rn.f16x2.f32 %0, %1, %2;" : "=r"(r) : "f"(hi), "f"(lo)); return r;
}
// split-fp16 of a float pair -> hi-pair u32 and lo-pair u32 (residuals; exact in fp32)
__device__ __forceinline__ void split2h(float a, float b, uint32_t& h, uint32_t& l) {
    h = h2pk(a, b);
    __half2 hh = *reinterpret_cast<__half2*>(&h);
    float fa = __low2float(hh), fb = __high2float(hh);
    l = h2pk(a - fa, b - fb);
}
__device__ __forceinline__ void mma_f16(float* d, uint32_t a0, uint32_t a1, uint32_t a2, uint32_t a3,
                                        uint32_t b0, uint32_t b1) {
    asm volatile(
        "mma.sync.aligned.m16n8k16.row.col.f32.f16.f16.f32 "
        "{%0,%1,%2,%3}, {%4,%5,%6,%7}, {%8,%9}, {%0,%1,%2,%3};"
        : "+f"(d[0]), "+f"(d[1]), "+f"(d[2]), "+f"(d[3])
        : "r"(a0), "r"(a1), "r"(a2), "r"(a3), "r"(b0), "r"(b1));
}

// smem tile geometry: 128 rows x 64 fp16 cols, row stride 144 bytes (72 fp16)
#define TS      144
#define TILE_B  (128 * TS)          // 18432
#define SM_AHI  0
#define SM_ALO  (TILE_B)
#define SM_BHI  (2 * TILE_B)
#define SM_MMA_TOTAL (3 * TILE_B)   // 55296 bytes -> 2 CTAs/SM (RF-bound anyway)

// GEMM core: scalar LDS.32 fragment loads, 2-term split-fp16 (A=hi+lo, B=hi only).
// Warp wm (0..3) owns rows wm*32..+31; warp wn (0..1) owns cols wn*64..+63.
__device__ __forceinline__ void mma_stage_compute(
    const char* smem, int wm, int wn, int g, int tg, float acc[2][8][4])
{
    #pragma unroll
    for (int kk = 0; kk < 4; kk++) {
        const int kb = kk * 32 + tg * 4;  // byte offset of k-pair (2tg) within 64-col tile
        uint32_t ah[2][4], al[2][4];
        #pragma unroll
        for (int i = 0; i < 2; i++) {
            int r0 = (wm * 32 + i * 16 + g) * TS + kb;
            int r1 = r0 + 8 * TS;
            ah[i][0] = *(const uint32_t*)(smem + SM_AHI + r0);
            ah[i][1] = *(const uint32_t*)(smem + SM_AHI + r1);
            ah[i][2] = *(const uint32_t*)(smem + SM_AHI + r0 + 16);
            ah[i][3] = *(const uint32_t*)(smem + SM_AHI + r1 + 16);
            al[i][0] = *(const uint32_t*)(smem + SM_ALO + r0);
            al[i][1] = *(const uint32_t*)(smem + SM_ALO + r1);
            al[i][2] = *(const uint32_t*)(smem + SM_ALO + r0 + 16);
            al[i][3] = *(const uint32_t*)(smem + SM_ALO + r1 + 16);
        }
        #pragma unroll
        for (int j = 0; j < 8; j++) {
            int rb = (wn * 64 + j * 8 + g) * TS + kb;
            uint32_t bh0 = *(const uint32_t*)(smem + SM_BHI + rb);
            uint32_t bh1 = *(const uint32_t*)(smem + SM_BHI + rb + 16);
            #pragma unroll
            for (int i = 0; i < 2; i++) {
                mma_f16(acc[i][j], ah[i][0], ah[i][1], ah[i][2], ah[i][3], bh0, bh1);
                mma_f16(acc[i][j], al[i][0], al[i][1], al[i][2], al[i][3], bh0, bh1);
            }
        }
    }
}

// ======================= K1: fused dual 1x1 GEMM + SiLU (mma.sync) =======================
// D[p][o] = sum_c x[b][c][p] * Wcat[o][c];  o<64 -> x1 (s1,b1), o>=64 -> x2 (s2,b2)
__global__ void __launch_bounds__(256, 2) k1_mma(
    const float* __restrict__ x,
    const float* __restrict__ w1, const float* __restrict__ s1, const float* __restrict__ b1,
    const float* __restrict__ w2, const float* __restrict__ s2, const float* __restrict__ b2)
{
    extern __shared__ char smem[];
    const int t = threadIdx.x, wid = t >> 5, lane = t & 31;
    const int g = lane >> 2, tg = lane & 3;
    const int wm = wid & 3, wn = wid >> 2;
    const int b = blockIdx.y, P = blockIdx.x << 7;

    float acc[2][8][4];
    #pragma unroll
    for (int i = 0; i < 2; i++)
        #pragma unroll
        for (int j = 0; j < 8; j++)
            #pragma unroll
            for (int q = 0; q < 4; q++) acc[i][j][q] = 0.f;

    const float* xb = x + b * (128 * HW) + P;

    #pragma unroll 1
    for (int s = 0; s < 2; s++) {
        // A: transpose x[c][p] -> rows = pixels, cols = channels (stage s: c in [s*64, s*64+64))
        for (int e = t; e < 2048; e += 256) {
            int r = e & 127, c4 = (e >> 7) << 2;
            const float* src = xb + (s * 64 + c4) * HW + r;
            float v0 = src[0], v1 = src[HW], v2 = src[2 * HW], v3 = src[3 * HW];
            uint32_t h01, l01, h23, l23;
            split2h(v0, v1, h01, l01);
            split2h(v2, v3, h23, l23);
            int off = r * TS + c4 * 2;
            *(uint32_t*)(smem + SM_AHI + off)     = h01;
            *(uint32_t*)(smem + SM_AHI + off + 4) = h23;
            *(uint32_t*)(smem + SM_ALO + off)     = l01;
            *(uint32_t*)(smem + SM_ALO + off + 4) = l23;
        }
        // B: Wcat rows, K-major direct (fp16 hi only)
        for (int e = t; e < 2048; e += 256) {
            int o = e >> 4, c4 = (e & 15) << 2;
            const float* src = (o < 64 ? w1 + o * 128 : w2 + (o - 64) * 128) + s * 64 + c4;
            float4 v = *(const float4*)src;
            int off = o * TS + c4 * 2;
            *(uint32_t*)(smem + SM_BHI + off)     = h2pk(v.x, v.y);
            *(uint32_t*)(smem + SM_BHI + off + 4) = h2pk(v.z, v.w);
        }
        __syncthreads();
        mma_stage_compute(smem, wm, wn, g, tg, acc);
        __syncthreads();
    }

    // Epilogue: acc[i][j] is 16x8 frag at (row wm*32+i*16, col wn*64+j*8)
    #pragma unroll
    for (int i = 0; i < 2; i++) {
        #pragma unroll
        for (int j = 0; j < 8; j++) {
            int o = wn * 64 + j * 8 + 2 * tg;
            bool first = (o < 64);
            int ob = o & 63;
            const float* sv = first ? s1 : s2;
            const float* bv = first ? b1 : b2;
            float sc0 = sv[ob], sc1 = sv[ob + 1];
            float bc0 = bv[ob], bc1 = bv[ob + 1];
            float* base = (first ? g_x1 : g_x2) + (b * HW) * 64;
            int p0 = P + wm * 32 + i * 16 + g;
            float2 r0, r1;
            r0.x = silu_f(fmaf(acc[i][j][0], sc0, bc0));
            r0.y = silu_f(fmaf(acc[i][j][1], sc1, bc1));
            r1.x = silu_f(fmaf(acc[i][j][2], sc0, bc0));
            r1.y = silu_f(fmaf(acc[i][j][3], sc1, bc1));
            *(float2*)(base + p0 * 64 + ob)        = r0;
            *(float2*)(base + (p0 + 8) * 64 + ob)  = r1;
        }
    }
}

// ======================= K2a: 3x3 offset conv (64 -> 18) =======================
#define K2A_SMEM ((612 * 33 + 32 * 9 * 20) * 4)
__global__ void __launch_bounds__(256) k2a_offconv(
    const float* __restrict__ off_w, const float* __restrict__ off_b)
{
    extern __shared__ float sm[];
    float* tile = sm;             // [(yy*34+xx)*33 + cL]  halo tile 18 x 34, 32 ch (pad 33)
    float* ws   = sm + 612 * 33;  // [(cL*9+k)*20 + oc]    oc padded to 20
    const int t  = threadIdx.x;
    const int bx = blockIdx.x << 5;
    const int by = blockIdx.y << 4;
    const int b  = blockIdx.z;

    const float* x1b = g_x1 + b * (HW * 64);

    const int lx = t & 15, ly = t >> 4;
    int spos[9];
    #pragma unroll
    for (int k = 0; k < 9; k++) {
        int ky = k / 3, kx = k - ky * 3;
        spos[k] = ((ly + ky) * 34 + (lx + kx)) * 33;
    }
    u64 acc0[9], acc1[9];
    #pragma unroll
    for (int j = 0; j < 9; j++) {
        u64 ib = pk2(off_b[2 * j], off_b[2 * j + 1]);
        acc0[j] = ib; acc1[j] = ib;
    }

    #pragma unroll 1
    for (int ch = 0; ch < 2; ch++) {
        for (int e4 = t; e4 < 612 * 8; e4 += 256) {
            int s = e4 >> 3, c4 = (e4 & 7) << 2;
            int yy = s / 34, xx = s - yy * 34;
            int gy = by + yy - 1, gx = bx + xx - 1;
            float4 v = make_float4(0.f, 0.f, 0.f, 0.f);
            if (gy >= 0 && gy < 128 && gx >= 0 && gx < 128)
                v = *(const float4*)(x1b + (gy * 128 + gx) * 64 + ch * 32 + c4);
            float* d = tile + s * 33 + c4;
            d[0] = v.x; d[1] = v.y; d[2] = v.z; d[3] = v.w;
        }
        for (int e = t; e < 18 * 288; e += 256) {
            int oc = e / 288, r = e - oc * 288;
            ws[r * 20 + oc] = off_w[oc * 576 + ch * 288 + r];
        }
        __syncthreads();

        for (int c = 0; c < 32; c++) {
            const float* wc = ws + c * 180;
            #pragma unroll
            for (int k = 0; k < 9; k++) {
                float v0 = tile[spos[k] + c];
                float v1 = tile[spos[k] + 16 * 33 + c];
                u64 p0 = pk2(v0, v0), p1 = pk2(v1, v1);
                const float* wr = wc + k * 20;
                ulonglong2 wa  = *(const ulonglong2*)(wr);
                ulonglong2 wb  = *(const ulonglong2*)(wr + 4);
                ulonglong2 wcv = *(const ulonglong2*)(wr + 8);
                ulonglong2 wd  = *(const ulonglong2*)(wr + 12);
                u64 we = *(const u64*)(wr + 16);
                u64 wv[9] = { wa.x, wa.y, wb.x, wb.y, wcv.x, wcv.y, wd.x, wd.y, we };
                #pragma unroll
                for (int j = 0; j < 9; j++) {
                    acc0[j] = f2fma(p0, wv[j], acc0[j]);
                    acc1[j] = f2fma(p1, wv[j], acc1[j]);
                }
            }
        }
        __syncthreads();
    }

    int p0 = (by + ly) * 128 + bx + lx;
    float* o0 = g_off + (b * HW + p0) * 18;
    float* o1 = o0 + 16 * 18;
    #pragma unroll
    for (int j = 0; j < 9; j++) {
        *(u64*)(o0 + 2 * j) = acc0[j];
        *(u64*)(o1 + 2 * j) = acc1[j];
    }
}

// ================ K2b: deformable bilinear sampling + depthwise =================
// ROUND-8 VERSION (measured best): warp per pixel; lane owns channel pair
__global__ void __launch_bounds__(256) k2b_sample(const float* __restrict__ dw)
{
    const int b = blockIdx.y;
    const int p = (blockIdx.x << 3) + (threadIdx.x >> 5);
    const int lane = threadIdx.x & 31;
    const int y = p >> 7, x = p & 127;
    const int c0 = lane << 1;

    u64 dwp[9];
    #pragma unroll
    for (int k = 0; k < 9; k++) dwp[k] = pk2(dw[c0 * 9 + k], dw[c0 * 9 + 9 + k]);

    const float* offp = g_off + (b * HW + p) * 18;
    float offv = (lane < 18) ? offp[lane] : 0.f;

    const float* x1b = g_x1 + b * (HW * 64) + c0;
    u64 acc = 0ULL;
    #pragma unroll
    for (int k = 0; k < 9; k++) {
        float dy = __shfl_sync(0xffffffffu, offv, 2 * k);
        float dx = __shfl_sync(0xffffffffu, offv, 2 * k + 1);
        float py = (float)(y + k / 3 - 1) + dy;
        float px = (float)(x + (k % 3) - 1) + dx;
        float y0f = floorf(py), x0f = floorf(px);
        float wy = py - y0f, wx = px - x0f;
        int y0 = (int)y0f, x0 = (int)x0f;
        bool yv0 = (y0 >= 0) && (y0 < 128);
        bool yv1 = (y0 + 1 >= 0) && (y0 + 1 < 128);
        bool xv0 = (x0 >= 0) && (x0 < 128);
        bool xv1 = (x0 + 1 >= 0) && (x0 + 1 < 128);
        u64 v00 = 0ULL, v01 = 0ULL, v10 = 0ULL, v11 = 0ULL;
        if (yv0 && xv0) v00 = *(const u64*)(x1b + (y0 * 128 + x0) * 64);
        if (yv0 && xv1) v01 = *(const u64*)(x1b + (y0 * 128 + x0 + 1) * 64);
        if (yv1 && xv0) v10 = *(const u64*)(x1b + ((y0 + 1) * 128 + x0) * 64);
        if (yv1 && xv1) v11 = *(const u64*)(x1b + ((y0 + 1) * 128 + x0 + 1) * 64);
        float omy = 1.f - wy, omx = 1.f - wx;
        u64 s = f2mul(v11, pk2(wy * wx, wy * wx));
        s = f2fma(v10, pk2(wy * omx, wy * omx), s);
        s = f2fma(v01, pk2(omy * wx, omy * wx), s);
        s = f2fma(v00, pk2(omy * omx, omy * omx), s);
        acc = f2fma(s, dwp[k], acc);
    }
    *(u64*)(g_d + (b * HW + p) * 64 + c0) = acc;
}

// ================== K4: final 1x1 GEMM over concat(d, x2) + SiLU (mma.sync) ==================
__global__ void __launch_bounds__(256, 2) k4_mma(
    const float* __restrict__ w3, const float* __restrict__ s3, const float* __restrict__ b3,
    float* __restrict__ out)
{
    extern __shared__ char smem[];
    const int t = threadIdx.x, wid = t >> 5, lane = t & 31;
    const int g = lane >> 2, tg = lane & 3;
    const int wm = wid & 3, wn = wid >> 2;
    const int b = blockIdx.y, P = blockIdx.x << 7;

    float acc[2][8][4];
    #pragma unroll
    for (int i = 0; i < 2; i++)
        #pragma unroll
        for (int j = 0; j < 8; j++)
            #pragma unroll
            for (int q = 0; q < 4; q++) acc[i][j][q] = 0.f;

    #pragma unroll 1
    for (int s = 0; s < 2; s++) {
        const float* abase = (s ? g_x2 : g_d) + (b * HW + P) * 64;
        // A: NHWC rows direct (row = pixel, cols = 64 channels of this stage)
        for (int e = t; e < 2048; e += 256) {
            int r = e >> 4, c4 = (e & 15) << 2;
            float4 v = *(const float4*)(abase + r * 64 + c4);
            uint32_t h01, l01, h23, l23;
            split2h(v.x, v.y, h01, l01);
            split2h(v.z, v.w, h23, l23);
            int off = r * TS + c4 * 2;
            *(uint32_t*)(smem + SM_AHI + off)     = h01;
            *(uint32_t*)(smem + SM_AHI + off + 4) = h23;
            *(uint32_t*)(smem + SM_ALO + off)     = l01;
            *(uint32_t*)(smem + SM_ALO + off + 4) = l23;
        }
        // B: w3 rows K-major direct (fp16 hi only)
        for (int e = t; e < 2048; e += 256) {
            int o = e >> 4, c4 = (e & 15) << 2;
            float4 v = *(const float4*)(w3 + o * 128 + s * 64 + c4);
            int off = o * TS + c4 * 2;
            *(uint32_t*)(smem + SM_BHI + off)     = h2pk(v.x, v.y);
            *(uint32_t*)(smem + SM_BHI + off + 4) = h2pk(v.z, v.w);
        }
        __syncthreads();
        mma_stage_compute(smem, wm, wn, g, tg, acc);
        __syncthreads();
    }

    // Epilogue: out is NCHW [b][o][p]
    #pragma unroll
    for (int i = 0; i < 2; i++) {
        #pragma unroll
        for (int j = 0; j < 8; j++) {
            int o = wn * 64 + j * 8 + 2 * tg;
            float sc0 = s3[o], sc1 = s3[o + 1];
            float bc0 = b3[o], bc1 = b3[o + 1];
            int p0 = P + wm * 32 + i * 16 + g;
            float* d0 = out + (b * 128 + o) * HW;
            float* d1 = out + (b * 128 + o + 1) * HW;
            d0[p0]     = silu_f(fmaf(acc[i][j][0], sc0, bc0));
            d1[p0]     = silu_f(fmaf(acc[i][j][1], sc1, bc1));
            d0[p0 + 8] = silu_f(fmaf(acc[i][j][2], sc0, bc0));
            d1[p0 + 8] = silu_f(fmaf(acc[i][j][3], sc1, bc1));
        }
    }
}

extern "C" void kernel_launch(void* const* d_in, const int* in_sizes, int n_in,
                              void* d_out, int out_size) {
    const float* x     = (const float*)d_in[0];
    const float* w1    = (const float*)d_in[1];
    const float* s1    = (const float*)d_in[2];
    const float* b1    = (const float*)d_in[3];
    const float* w2    = (const float*)d_in[4];
    const float* s2    = (const float*)d_in[5];
    const float* b2    = (const float*)d_in[6];
    const float* w3    = (const float*)d_in[7];
    const float* s3    = (const float*)d_in[8];
    const float* b3    = (const float*)d_in[9];
    const float* off_w = (const float*)d_in[10];
    const float* off_b = (const float*)d_in[11];
    const float* dw    = (const float*)d_in[12];
    float* out = (float*)d_out;

    cudaFuncSetAttribute(k1_mma, cudaFuncAttributeMaxDynamicSharedMemorySize, SM_MMA_TOTAL);
    cudaFuncSetAttribute(k2a_offconv, cudaFuncAttributeMaxDynamicSharedMemorySize, K2A_SMEM);
    cudaFuncSetAttribute(k4_mma, cudaFuncAttributeMaxDynamicSharedMemorySize, SM_MMA_TOTAL);

    dim3 g1(HW / 128, BATCH);
    k1_mma<<<g1, 256, SM_MMA_TOTAL>>>(x, w1, s1, b1, w2, s2, b2);

    dim3 g2a(128 / 32, 128 / 16, BATCH);
    k2a_offconv<<<g2a, 256, K2A_SMEM>>>(off_w, off_b);

    dim3 g2b(HW / 8, BATCH);
    k2b_sample<<<g2b, 256>>>(dw);

    dim3 g4(HW / 128, BATCH);
    k4_mma<<<g4, 256, SM_MMA_TOTAL>>>(w3, s3, b3, out);
}

// round 16
// speedup vs baseline: 1.3179x; 1.0647x over previous
#include <cuda_runtime.h>
#include <cuda_bf16.h>
#include <cuda_fp16.h>
#include <cstdint>

#define BATCH 8
#define HW    16384
#define HID   64

// ---------------- scratch (static device memory; no allocations) ----------------
__device__ float g_x1[BATCH * HW * HID];   // NHWC: [b][p][c]
__device__ float g_x2[BATCH * HW * HID];   // NHWC
__device__ float g_off[BATCH * HW * 18];   // [b][p][18]
__device__ float g_d [BATCH * HW * HID];   // NHWC

typedef unsigned long long u64;

__device__ __forceinline__ u64 pk2(float lo, float hi) {
    u64 r; asm("mov.b64 %0, {%1,%2};" : "=l"(r) : "f"(lo), "f"(hi)); return r;
}
__device__ __forceinline__ u64 f2fma(u64 a, u64 b, u64 c) {
    u64 d; asm("fma.rn.f32x2 %0,%1,%2,%3;" : "=l"(d) : "l"(a), "l"(b), "l"(c)); return d;
}
__device__ __forceinline__ u64 f2mul(u64 a, u64 b) {
    u64 d; asm("mul.rn.f32x2 %0,%1,%2;" : "=l"(d) : "l"(a), "l"(b)); return d;
}
__device__ __forceinline__ float silu_f(float v) {
    return __fdividef(v, 1.0f + __expf(-v));
}

// ---------------- mma.sync helpers (baseline PTX; works on compute_103) ----------------
// fp16x2 pack: lo -> low half, hi -> high half
__device__ __forceinline__ uint32_t h2pk(float lo, float hi) {
    uint32_t r; asm("cvt.rn.f16x2.f32 %0, %1, %2;" : "=r"(r) : "f"(hi), "f"(lo)); return r;
}
// split-fp16 of a float pair -> hi-pair u32 and lo-pair u32 (residuals; exact in fp32)
__device__ __forceinline__ void split2h(float a, float b, uint32_t& h, uint32_t& l) {
    h = h2pk(a, b);
    __half2 hh = *reinterpret_cast<__half2*>(&h);
    float fa = __low2float(hh), fb = __high2float(hh);
    l = h2pk(a - fa, b - fb);
}
__device__ __forceinline__ void mma_f16(float* d, uint32_t a0, uint32_t a1, uint32_t a2, uint32_t a3,
                                        uint32_t b0, uint32_t b1) {
    asm volatile(
        "mma.sync.aligned.m16n8k16.row.col.f32.f16.f16.f32 "
        "{%0,%1,%2,%3}, {%4,%5,%6,%7}, {%8,%9}, {%0,%1,%2,%3};"
        : "+f"(d[0]), "+f"(d[1]), "+f"(d[2]), "+f"(d[3])
        : "r"(a0), "r"(a1), "r"(a2), "r"(a3), "r"(b0), "r"(b1));
}

// smem tile geometry: 128 rows x 64 fp16 cols, row stride 144 bytes (72 fp16)
#define TS      144
#define TILE_B  (128 * TS)          // 18432
#define SM_AHI  0
#define SM_ALO  (TILE_B)
#define SM_BHI  (2 * TILE_B)
#define SM_MMA_TOTAL (3 * TILE_B)   // 55296 bytes -> 2 CTAs/SM

// GEMM core: scalar LDS.32 fragment loads, 2-term split-fp16 (A=hi+lo, B=hi only).
__device__ __forceinline__ void mma_stage_compute(
    const char* smem, int wm, int wn, int g, int tg, float acc[2][8][4])
{
    #pragma unroll
    for (int kk = 0; kk < 4; kk++) {
        const int kb = kk * 32 + tg * 4;  // byte offset of k-pair (2tg) within 64-col tile
        uint32_t ah[2][4], al[2][4];
        #pragma unroll
        for (int i = 0; i < 2; i++) {
            int r0 = (wm * 32 + i * 16 + g) * TS + kb;
            int r1 = r0 + 8 * TS;
            ah[i][0] = *(const uint32_t*)(smem + SM_AHI + r0);
            ah[i][1] = *(const uint32_t*)(smem + SM_AHI + r1);
            ah[i][2] = *(const uint32_t*)(smem + SM_AHI + r0 + 16);
            ah[i][3] = *(const uint32_t*)(smem + SM_AHI + r1 + 16);
            al[i][0] = *(const uint32_t*)(smem + SM_ALO + r0);
            al[i][1] = *(const uint32_t*)(smem + SM_ALO + r1);
            al[i][2] = *(const uint32_t*)(smem + SM_ALO + r0 + 16);
            al[i][3] = *(const uint32_t*)(smem + SM_ALO + r1 + 16);
        }
        #pragma unroll
        for (int j = 0; j < 8; j++) {
            int rb = (wn * 64 + j * 8 + g) * TS + kb;
            uint32_t bh0 = *(const uint32_t*)(smem + SM_BHI + rb);
            uint32_t bh1 = *(const uint32_t*)(smem + SM_BHI + rb + 16);
            #pragma unroll
            for (int i = 0; i < 2; i++) {
                mma_f16(acc[i][j], ah[i][0], ah[i][1], ah[i][2], ah[i][3], bh0, bh1);
                mma_f16(acc[i][j], al[i][0], al[i][1], al[i][2], al[i][3], bh0, bh1);
            }
        }
    }
}

// ======================= K1: fused dual 1x1 GEMM + SiLU (mma.sync) =======================
__global__ void __launch_bounds__(256, 2) k1_mma(
    const float* __restrict__ x,
    const float* __restrict__ w1, const float* __restrict__ s1, const float* __restrict__ b1,
    const float* __restrict__ w2, const float* __restrict__ s2, const float* __restrict__ b2)
{
    extern __shared__ char smem[];
    const int t = threadIdx.x, wid = t >> 5, lane = t & 31;
    const int g = lane >> 2, tg = lane & 3;
    const int wm = wid & 3, wn = wid >> 2;
    const int b = blockIdx.y, P = blockIdx.x << 7;

    float acc[2][8][4];
    #pragma unroll
    for (int i = 0; i < 2; i++)
        #pragma unroll
        for (int j = 0; j < 8; j++)
            #pragma unroll
            for (int q = 0; q < 4; q++) acc[i][j][q] = 0.f;

    const float* xb = x + b * (128 * HW) + P;

    #pragma unroll 1
    for (int s = 0; s < 2; s++) {
        for (int e = t; e < 2048; e += 256) {
            int r = e & 127, c4 = (e >> 7) << 2;
            const float* src = xb + (s * 64 + c4) * HW + r;
            float v0 = src[0], v1 = src[HW], v2 = src[2 * HW], v3 = src[3 * HW];
            uint32_t h01, l01, h23, l23;
            split2h(v0, v1, h01, l01);
            split2h(v2, v3, h23, l23);
            int off = r * TS + c4 * 2;
            *(uint32_t*)(smem + SM_AHI + off)     = h01;
            *(uint32_t*)(smem + SM_AHI + off + 4) = h23;
            *(uint32_t*)(smem + SM_ALO + off)     = l01;
            *(uint32_t*)(smem + SM_ALO + off + 4) = l23;
        }
        for (int e = t; e < 2048; e += 256) {
            int o = e >> 4, c4 = (e & 15) << 2;
            const float* src = (o < 64 ? w1 + o * 128 : w2 + (o - 64) * 128) + s * 64 + c4;
            float4 v = *(const float4*)src;
            int off = o * TS + c4 * 2;
            *(uint32_t*)(smem + SM_BHI + off)     = h2pk(v.x, v.y);
            *(uint32_t*)(smem + SM_BHI + off + 4) = h2pk(v.z, v.w);
        }
        __syncthreads();
        mma_stage_compute(smem, wm, wn, g, tg, acc);
        __syncthreads();
    }

    #pragma unroll
    for (int i = 0; i < 2; i++) {
        #pragma unroll
        for (int j = 0; j < 8; j++) {
            int o = wn * 64 + j * 8 + 2 * tg;
            bool first = (o < 64);
            int ob = o & 63;
            const float* sv = first ? s1 : s2;
            const float* bv = first ? b1 : b2;
            float sc0 = sv[ob], sc1 = sv[ob + 1];
            float bc0 = bv[ob], bc1 = bv[ob + 1];
            float* base = (first ? g_x1 : g_x2) + (b * HW) * 64;
            int p0 = P + wm * 32 + i * 16 + g;
            float2 r0, r1;
            r0.x = silu_f(fmaf(acc[i][j][0], sc0, bc0));
            r0.y = silu_f(fmaf(acc[i][j][1], sc1, bc1));
            r1.x = silu_f(fmaf(acc[i][j][2], sc0, bc0));
            r1.y = silu_f(fmaf(acc[i][j][3], sc1, bc1));
            *(float2*)(base + p0 * 64 + ob)        = r0;
            *(float2*)(base + (p0 + 8) * 64 + ob)  = r1;
        }
    }
}

// ======================= K2a: 3x3 offset conv (64 -> 18) =======================
#define K2A_SMEM ((612 * 33 + 32 * 9 * 20) * 4)
__global__ void __launch_bounds__(256) k2a_offconv(
    const float* __restrict__ off_w, const float* __restrict__ off_b)
{
    extern __shared__ float sm[];
    float* tile = sm;             // [(yy*34+xx)*33 + cL]  halo tile 18 x 34, 32 ch (pad 33)
    float* ws   = sm + 612 * 33;  // [(cL*9+k)*20 + oc]    oc padded to 20
    const int t  = threadIdx.x;
    const int bx = blockIdx.x << 5;
    const int by = blockIdx.y << 4;
    const int b  = blockIdx.z;

    const float* x1b = g_x1 + b * (HW * 64);

    const int lx = t & 15, ly = t >> 4;
    int spos[9];
    #pragma unroll
    for (int k = 0; k < 9; k++) {
        int ky = k / 3, kx = k - ky * 3;
        spos[k] = ((ly + ky) * 34 + (lx + kx)) * 33;
    }
    u64 acc0[9], acc1[9];
    #pragma unroll
    for (int j = 0; j < 9; j++) {
        u64 ib = pk2(off_b[2 * j], off_b[2 * j + 1]);
        acc0[j] = ib; acc1[j] = ib;
    }

    #pragma unroll 1
    for (int ch = 0; ch < 2; ch++) {
        for (int e4 = t; e4 < 612 * 8; e4 += 256) {
            int s = e4 >> 3, c4 = (e4 & 7) << 2;
            int yy = s / 34, xx = s - yy * 34;
            int gy = by + yy - 1, gx = bx + xx - 1;
            float4 v = make_float4(0.f, 0.f, 0.f, 0.f);
            if (gy >= 0 && gy < 128 && gx >= 0 && gx < 128)
                v = *(const float4*)(x1b + (gy * 128 + gx) * 64 + ch * 32 + c4);
            float* d = tile + s * 33 + c4;
            d[0] = v.x; d[1] = v.y; d[2] = v.z; d[3] = v.w;
        }
        for (int e = t; e < 18 * 288; e += 256) {
            int oc = e / 288, r = e - oc * 288;
            ws[r * 20 + oc] = off_w[oc * 576 + ch * 288 + r];
        }
        __syncthreads();

        for (int c = 0; c < 32; c++) {
            const float* wc = ws + c * 180;
            #pragma unroll
            for (int k = 0; k < 9; k++) {
                float v0 = tile[spos[k] + c];
                float v1 = tile[spos[k] + 16 * 33 + c];
                u64 p0 = pk2(v0, v0), p1 = pk2(v1, v1);
                const float* wr = wc + k * 20;
                ulonglong2 wa  = *(const ulonglong2*)(wr);
                ulonglong2 wb  = *(const ulonglong2*)(wr + 4);
                ulonglong2 wcv = *(const ulonglong2*)(wr + 8);
                ulonglong2 wd  = *(const ulonglong2*)(wr + 12);
                u64 we = *(const u64*)(wr + 16);
                u64 wv[9] = { wa.x, wa.y, wb.x, wb.y, wcv.x, wcv.y, wd.x, wd.y, we };
                #pragma unroll
                for (int j = 0; j < 9; j++) {
                    acc0[j] = f2fma(p0, wv[j], acc0[j]);
                    acc1[j] = f2fma(p1, wv[j], acc1[j]);
                }
            }
        }
        __syncthreads();
    }

    int p0 = (by + ly) * 128 + bx + lx;
    float* o0 = g_off + (b * HW + p0) * 18;
    float* o1 = o0 + 16 * 18;
    #pragma unroll
    for (int j = 0; j < 9; j++) {
        *(u64*)(o0 + 2 * j) = acc0[j];
        *(u64*)(o1 + 2 * j) = acc1[j];
    }
}

// ================ K2b: deformable bilinear sampling + depthwise =================
// 2 pixels per warp: lanes 0-15 pixel pA (4 ch/lane, LDG.128), lanes 16-31 pixel pA+1.
// Halves warp-level LDG instruction count vs 1-px/warp (36 -> 18 per pixel).
__global__ void __launch_bounds__(256) k2b_sample(const float* __restrict__ dw)
{
    const int b = blockIdx.y;
    const int wid = threadIdx.x >> 5, lane = threadIdx.x & 31;
    const int half = lane >> 4;                       // 0 -> pixel pA, 1 -> pixel pA+1
    const int pA = (blockIdx.x << 4) + (wid << 1);    // 8 warps * 2 px = 16 px per CTA
    const int p  = pA + half;
    const int y = p >> 7, x = p & 127;
    const int c0 = (lane & 15) << 2;                  // 4 channels per lane

    u64 dwp0[9], dwp1[9];
    #pragma unroll
    for (int k = 0; k < 9; k++) {
        dwp0[k] = pk2(dw[(c0 + 0) * 9 + k], dw[(c0 + 1) * 9 + k]);
        dwp1[k] = pk2(dw[(c0 + 2) * 9 + k], dw[(c0 + 3) * 9 + k]);
    }

    // offsets for both pixels of the pair (contiguous in g_off)
    const float* offA = g_off + (b * HW + pA) * 18;
    float ovA = (lane < 18) ? offA[lane] : 0.f;
    float ovB = (lane < 18) ? offA[18 + lane] : 0.f;

    const float* x1b = g_x1 + b * (HW * 64) + c0;
    u64 acc0 = 0ULL, acc1 = 0ULL;
    #pragma unroll
    for (int k = 0; k < 9; k++) {
        float dyA = __shfl_sync(0xffffffffu, ovA, 2 * k);
        float dxA = __shfl_sync(0xffffffffu, ovA, 2 * k + 1);
        float dyB = __shfl_sync(0xffffffffu, ovB, 2 * k);
        float dxB = __shfl_sync(0xffffffffu, ovB, 2 * k + 1);
        float dy = half ? dyB : dyA;
        float dx = half ? dxB : dxA;
        float py = (float)(y + k / 3 - 1) + dy;
        float px = (float)(x + (k % 3) - 1) + dx;
        float y0f = floorf(py), x0f = floorf(px);
        float wy = py - y0f, wx = px - x0f;
        int y0 = (int)y0f, x0 = (int)x0f;
        bool yv0 = (y0 >= 0) && (y0 < 128);
        bool yv1 = (y0 + 1 >= 0) && (y0 + 1 < 128);
        bool xv0 = (x0 >= 0) && (x0 < 128);
        bool xv1 = (x0 + 1 >= 0) && (x0 + 1 < 128);
        ulonglong2 z = make_ulonglong2(0ULL, 0ULL);
        ulonglong2 v00 = z, v01 = z, v10 = z, v11 = z;
        if (yv0 && xv0) v00 = *(const ulonglong2*)(x1b + (y0 * 128 + x0) * 64);
        if (yv0 && xv1) v01 = *(const ulonglong2*)(x1b + (y0 * 128 + x0 + 1) * 64);
        if (yv1 && xv0) v10 = *(const ulonglong2*)(x1b + ((y0 + 1) * 128 + x0) * 64);
        if (yv1 && xv1) v11 = *(const ulonglong2*)(x1b + ((y0 + 1) * 128 + x0 + 1) * 64);
        float omy = 1.f - wy, omx = 1.f - wx;
        u64 w11 = pk2(wy * wx,  wy * wx);
        u64 w10 = pk2(wy * omx, wy * omx);
        u64 w01 = pk2(omy * wx, omy * wx);
        u64 w00 = pk2(omy * omx, omy * omx);
        u64 s0 = f2mul(v11.x, w11);
        s0 = f2fma(v10.x, w10, s0);
        s0 = f2fma(v01.x, w01, s0);
        s0 = f2fma(v00.x, w00, s0);
        u64 s1 = f2mul(v11.y, w11);
        s1 = f2fma(v10.y, w10, s1);
        s1 = f2fma(v01.y, w01, s1);
        s1 = f2fma(v00.y, w00, s1);
        acc0 = f2fma(s0, dwp0[k], acc0);
        acc1 = f2fma(s1, dwp1[k], acc1);
    }
    *(ulonglong2*)(g_d + (b * HW + p) * 64 + c0) = make_ulonglong2(acc0, acc1);
}

// ================== K4: final 1x1 GEMM over concat(d, x2) + SiLU (mma.sync) ==================
__global__ void __launch_bounds__(256, 2) k4_mma(
    const float* __restrict__ w3, const float* __restrict__ s3, const float* __restrict__ b3,
    float* __restrict__ out)
{
    extern __shared__ char smem[];
    const int t = threadIdx.x, wid = t >> 5, lane = t & 31;
    const int g = lane >> 2, tg = lane & 3;
    const int wm = wid & 3, wn = wid >> 2;
    const int b = blockIdx.y, P = blockIdx.x << 7;

    float acc[2][8][4];
    #pragma unroll
    for (int i = 0; i < 2; i++)
        #pragma unroll
        for (int j = 0; j < 8; j++)
            #pragma unroll
            for (int q = 0; q < 4; q++) acc[i][j][q] = 0.f;

    #pragma unroll 1
    for (int s = 0; s < 2; s++) {
        const float* abase = (s ? g_x2 : g_d) + (b * HW + P) * 64;
        for (int e = t; e < 2048; e += 256) {
            int r = e >> 4, c4 = (e & 15) << 2;
            float4 v = *(const float4*)(abase + r * 64 + c4);
            uint32_t h01, l01, h23, l23;
            split2h(v.x, v.y, h01, l01);
            split2h(v.z, v.w, h23, l23);
            int off = r * TS + c4 * 2;
            *(uint32_t*)(smem + SM_AHI + off)     = h01;
            *(uint32_t*)(smem + SM_AHI + off + 4) = h23;
            *(uint32_t*)(smem + SM_ALO + off)     = l01;
            *(uint32_t*)(smem + SM_ALO + off + 4) = l23;
        }
        for (int e = t; e < 2048; e += 256) {
            int o = e >> 4, c4 = (e & 15) << 2;
            float4 v = *(const float4*)(w3 + o * 128 + s * 64 + c4);
            int off = o * TS + c4 * 2;
            *(uint32_t*)(smem + SM_BHI + off)     = h2pk(v.x, v.y);
            *(uint32_t*)(smem + SM_BHI + off + 4) = h2pk(v.z, v.w);
        }
        __syncthreads();
        mma_stage_compute(smem, wm, wn, g, tg, acc);
        __syncthreads();
    }

    #pragma unroll
    for (int i = 0; i < 2; i++) {
        #pragma unroll
        for (int j = 0; j < 8; j++) {
            int o = wn * 64 + j * 8 + 2 * tg;
            float sc0 = s3[o], sc1 = s3[o + 1];
            float bc0 = b3[o], bc1 = b3[o + 1];
            int p0 = P + wm * 32 + i * 16 + g;
            float* d0 = out + (b * 128 + o) * HW;
            float* d1 = out + (b * 128 + o + 1) * HW;
            d0[p0]     = silu_f(fmaf(acc[i][j][0], sc0, bc0));
            d1[p0]     = silu_f(fmaf(acc[i][j][1], sc1, bc1));
            d0[p0 + 8] = silu_f(fmaf(acc[i][j][2], sc0, bc0));
            d1[p0 + 8] = silu_f(fmaf(acc[i][j][3], sc1, bc1));
        }
    }
}

extern "C" void kernel_launch(void* const* d_in, const int* in_sizes, int n_in,
                              void* d_out, int out_size) {
    const float* x     = (const float*)d_in[0];
    const float* w1    = (const float*)d_in[1];
    const float* s1    = (const float*)d_in[2];
    const float* b1    = (const float*)d_in[3];
    const float* w2    = (const float*)d_in[4];
    const float* s2    = (const float*)d_in[5];
    const float* b2    = (const float*)d_in[6];
    const float* w3    = (const float*)d_in[7];
    const float* s3    = (const float*)d_in[8];
    const float* b3    = (const float*)d_in[9];
    const float* off_w = (const float*)d_in[10];
    const float* off_b = (const float*)d_in[11];
    const float* dw    = (const float*)d_in[12];
    float* out = (float*)d_out;

    cudaFuncSetAttribute(k1_mma, cudaFuncAttributeMaxDynamicSharedMemorySize, SM_MMA_TOTAL);
    cudaFuncSetAttribute(k2a_offconv, cudaFuncAttributeMaxDynamicSharedMemorySize, K2A_SMEM);
    cudaFuncSetAttribute(k4_mma, cudaFuncAttributeMaxDynamicSharedMemorySize, SM_MMA_TOTAL);

    dim3 g1(HW / 128, BATCH);
    k1_mma<<<g1, 256, SM_MMA_TOTAL>>>(x, w1, s1, b1, w2, s2, b2);

    dim3 g2a(128 / 32, 128 / 16, BATCH);
    k2a_offconv<<<g2a, 256, K2A_SMEM>>>(off_w, off_b);

    dim3 g2b(HW / 16, BATCH);
    k2b_sample<<<g2b, 256>>>(dw);

    dim3 g4(HW / 128, BATCH);
    k4_mma<<<g4, 256, SM_MMA_TOTAL>>>(w3, s3, b3, out);
}

// round 17
// speedup vs baseline: 1.3879x; 1.0531x over previous
#include <cuda_runtime.h>
#include <cuda_bf16.h>
#include <cuda_fp16.h>
#include <cstdint>

#define BATCH 8
#define HW    16384
#define HID   64

// ---------------- scratch (static device memory; no allocations) ----------------
__device__ float g_x1[BATCH * HW * HID];   // NHWC: [b][p][c]
__device__ float g_x2[BATCH * HW * HID];   // NHWC
__device__ float g_off[BATCH * HW * 18];   // [b][p][18]
__device__ float g_d [BATCH * HW * HID];   // NHWC

typedef unsigned long long u64;

__device__ __forceinline__ u64 pk2(float lo, float hi) {
    u64 r; asm("mov.b64 %0, {%1,%2};" : "=l"(r) : "f"(lo), "f"(hi)); return r;
}
__device__ __forceinline__ u64 f2fma(u64 a, u64 b, u64 c) {
    u64 d; asm("fma.rn.f32x2 %0,%1,%2,%3;" : "=l"(d) : "l"(a), "l"(b), "l"(c)); return d;
}
__device__ __forceinline__ u64 f2mul(u64 a, u64 b) {
    u64 d; asm("mul.rn.f32x2 %0,%1,%2;" : "=l"(d) : "l"(a), "l"(b)); return d;
}
__device__ __forceinline__ float silu_f(float v) {
    return __fdividef(v, 1.0f + __expf(-v));
}

// ---------------- mma.sync helpers (baseline PTX; works on compute_103) ----------------
// fp16x2 pack: lo -> low half, hi -> high half
__device__ __forceinline__ uint32_t h2pk(float lo, float hi) {
    uint32_t r; asm("cvt.rn.f16x2.f32 %0, %1, %2;" : "=r"(r) : "f"(hi), "f"(lo)); return r;
}
__device__ __forceinline__ void mma_f16(float* d, uint32_t a0, uint32_t a1, uint32_t a2, uint32_t a3,
                                        uint32_t b0, uint32_t b1) {
    asm volatile(
        "mma.sync.aligned.m16n8k16.row.col.f32.f16.f16.f32 "
        "{%0,%1,%2,%3}, {%4,%5,%6,%7}, {%8,%9}, {%0,%1,%2,%3};"
        : "+f"(d[0]), "+f"(d[1]), "+f"(d[2]), "+f"(d[3])
        : "r"(a0), "r"(a1), "r"(a2), "r"(a3), "r"(b0), "r"(b1));
}

// smem tile geometry: 128 rows x 64 fp16 cols, row stride 144 bytes (72 fp16)
#define TS      144
#define TILE_B  (128 * TS)          // 18432
#define SM_A    0
#define SM_B    (TILE_B)
#define SM_MMA_TOTAL (2 * TILE_B)   // 36864 bytes

// GEMM core: scalar LDS.32 fragment loads, single-term fp16 (A and B fp16-rounded).
// Warp wm (0..3) owns rows wm*32..+31; warp wn (0..1) owns cols wn*64..+63.
__device__ __forceinline__ void mma_stage_compute(
    const char* smem, int wm, int wn, int g, int tg, float acc[2][8][4])
{
    #pragma unroll
    for (int kk = 0; kk < 4; kk++) {
        const int kb = kk * 32 + tg * 4;  // byte offset of k-pair (2tg) within 64-col tile
        uint32_t ah[2][4];
        #pragma unroll
        for (int i = 0; i < 2; i++) {
            int r0 = (wm * 32 + i * 16 + g) * TS + kb;
            int r1 = r0 + 8 * TS;
            ah[i][0] = *(const uint32_t*)(smem + SM_A + r0);
            ah[i][1] = *(const uint32_t*)(smem + SM_A + r1);
            ah[i][2] = *(const uint32_t*)(smem + SM_A + r0 + 16);
            ah[i][3] = *(const uint32_t*)(smem + SM_A + r1 + 16);
        }
        #pragma unroll
        for (int j = 0; j < 8; j++) {
            int rb = (wn * 64 + j * 8 + g) * TS + kb;
            uint32_t bh0 = *(const uint32_t*)(smem + SM_B + rb);
            uint32_t bh1 = *(const uint32_t*)(smem + SM_B + rb + 16);
            #pragma unroll
            for (int i = 0; i < 2; i++) {
                mma_f16(acc[i][j], ah[i][0], ah[i][1], ah[i][2], ah[i][3], bh0, bh1);
            }
        }
    }
}

// ======================= K1: fused dual 1x1 GEMM + SiLU (mma.sync) =======================
// D[p][o] = sum_c x[b][c][p] * Wcat[o][c];  o<64 -> x1 (s1,b1), o>=64 -> x2 (s2,b2)
__global__ void __launch_bounds__(256, 2) k1_mma(
    const float* __restrict__ x,
    const float* __restrict__ w1, const float* __restrict__ s1, const float* __restrict__ b1,
    const float* __restrict__ w2, const float* __restrict__ s2, const float* __restrict__ b2)
{
    extern __shared__ char smem[];
    const int t = threadIdx.x, wid = t >> 5, lane = t & 31;
    const int g = lane >> 2, tg = lane & 3;
    const int wm = wid & 3, wn = wid >> 2;
    const int b = blockIdx.y, P = blockIdx.x << 7;

    float acc[2][8][4];
    #pragma unroll
    for (int i = 0; i < 2; i++)
        #pragma unroll
        for (int j = 0; j < 8; j++)
            #pragma unroll
            for (int q = 0; q < 4; q++) acc[i][j][q] = 0.f;

    const float* xb = x + b * (128 * HW) + P;

    #pragma unroll 1
    for (int s = 0; s < 2; s++) {
        // A: transpose x[c][p] -> rows = pixels, cols = channels (stage s: c in [s*64, s*64+64))
        for (int e = t; e < 2048; e += 256) {
            int r = e & 127, c4 = (e >> 7) << 2;
            const float* src = xb + (s * 64 + c4) * HW + r;
            float v0 = src[0], v1 = src[HW], v2 = src[2 * HW], v3 = src[3 * HW];
            int off = r * TS + c4 * 2;
            *(uint32_t*)(smem + SM_A + off)     = h2pk(v0, v1);
            *(uint32_t*)(smem + SM_A + off + 4) = h2pk(v2, v3);
        }
        // B: Wcat rows, K-major direct (fp16)
        for (int e = t; e < 2048; e += 256) {
            int o = e >> 4, c4 = (e & 15) << 2;
            const float* src = (o < 64 ? w1 + o * 128 : w2 + (o - 64) * 128) + s * 64 + c4;
            float4 v = *(const float4*)src;
            int off = o * TS + c4 * 2;
            *(uint32_t*)(smem + SM_B + off)     = h2pk(v.x, v.y);
            *(uint32_t*)(smem + SM_B + off + 4) = h2pk(v.z, v.w);
        }
        __syncthreads();
        mma_stage_compute(smem, wm, wn, g, tg, acc);
        __syncthreads();
    }

    // Epilogue: acc[i][j] is 16x8 frag at (row wm*32+i*16, col wn*64+j*8)
    #pragma unroll
    for (int i = 0; i < 2; i++) {
        #pragma unroll
        for (int j = 0; j < 8; j++) {
            int o = wn * 64 + j * 8 + 2 * tg;
            bool first = (o < 64);
            int ob = o & 63;
            const float* sv = first ? s1 : s2;
            const float* bv = first ? b1 : b2;
            float sc0 = sv[ob], sc1 = sv[ob + 1];
            float bc0 = bv[ob], bc1 = bv[ob + 1];
            float* base = (first ? g_x1 : g_x2) + (b * HW) * 64;
            int p0 = P + wm * 32 + i * 16 + g;
            float2 r0, r1;
            r0.x = silu_f(fmaf(acc[i][j][0], sc0, bc0));
            r0.y = silu_f(fmaf(acc[i][j][1], sc1, bc1));
            r1.x = silu_f(fmaf(acc[i][j][2], sc0, bc0));
            r1.y = silu_f(fmaf(acc[i][j][3], sc1, bc1));
            *(float2*)(base + p0 * 64 + ob)        = r0;
            *(float2*)(base + (p0 + 8) * 64 + ob)  = r1;
        }
    }
}

// ======================= K2a: 3x3 offset conv (64 -> 18) =======================
#define K2A_SMEM ((612 * 33 + 32 * 9 * 20) * 4)
__global__ void __launch_bounds__(256) k2a_offconv(
    const float* __restrict__ off_w, const float* __restrict__ off_b)
{
    extern __shared__ float sm[];
    float* tile = sm;             // [(yy*34+xx)*33 + cL]  halo tile 18 x 34, 32 ch (pad 33)
    float* ws   = sm + 612 * 33;  // [(cL*9+k)*20 + oc]    oc padded to 20
    const int t  = threadIdx.x;
    const int bx = blockIdx.x << 5;
    const int by = blockIdx.y << 4;
    const int b  = blockIdx.z;

    const float* x1b = g_x1 + b * (HW * 64);

    const int lx = t & 15, ly = t >> 4;
    int spos[9];
    #pragma unroll
    for (int k = 0; k < 9; k++) {
        int ky = k / 3, kx = k - ky * 3;
        spos[k] = ((ly + ky) * 34 + (lx + kx)) * 33;
    }
    u64 acc0[9], acc1[9];
    #pragma unroll
    for (int j = 0; j < 9; j++) {
        u64 ib = pk2(off_b[2 * j], off_b[2 * j + 1]);
        acc0[j] = ib; acc1[j] = ib;
    }

    #pragma unroll 1
    for (int ch = 0; ch < 2; ch++) {
        for (int e4 = t; e4 < 612 * 8; e4 += 256) {
            int s = e4 >> 3, c4 = (e4 & 7) << 2;
            int yy = s / 34, xx = s - yy * 34;
            int gy = by + yy - 1, gx = bx + xx - 1;
            float4 v = make_float4(0.f, 0.f, 0.f, 0.f);
            if (gy >= 0 && gy < 128 && gx >= 0 && gx < 128)
                v = *(const float4*)(x1b + (gy * 128 + gx) * 64 + ch * 32 + c4);
            float* d = tile + s * 33 + c4;
            d[0] = v.x; d[1] = v.y; d[2] = v.z; d[3] = v.w;
        }
        for (int e = t; e < 18 * 288; e += 256) {
            int oc = e / 288, r = e - oc * 288;
            ws[r * 20 + oc] = off_w[oc * 576 + ch * 288 + r];
        }
        __syncthreads();

        for (int c = 0; c < 32; c++) {
            const float* wc = ws + c * 180;
            #pragma unroll
            for (int k = 0; k < 9; k++) {
                float v0 = tile[spos[k] + c];
                float v1 = tile[spos[k] + 16 * 33 + c];
                u64 p0 = pk2(v0, v0), p1 = pk2(v1, v1);
                const float* wr = wc + k * 20;
                ulonglong2 wa  = *(const ulonglong2*)(wr);
                ulonglong2 wb  = *(const ulonglong2*)(wr + 4);
                ulonglong2 wcv = *(const ulonglong2*)(wr + 8);
                ulonglong2 wd  = *(const ulonglong2*)(wr + 12);
                u64 we = *(const u64*)(wr + 16);
                u64 wv[9] = { wa.x, wa.y, wb.x, wb.y, wcv.x, wcv.y, wd.x, wd.y, we };
                #pragma unroll
                for (int j = 0; j < 9; j++) {
                    acc0[j] = f2fma(p0, wv[j], acc0[j]);
                    acc1[j] = f2fma(p1, wv[j], acc1[j]);
                }
            }
        }
        __syncthreads();
    }

    int p0 = (by + ly) * 128 + bx + lx;
    float* o0 = g_off + (b * HW + p0) * 18;
    float* o1 = o0 + 16 * 18;
    #pragma unroll
    for (int j = 0; j < 9; j++) {
        *(u64*)(o0 + 2 * j) = acc0[j];
        *(u64*)(o1 + 2 * j) = acc1[j];
    }
}

// ================ K2b: deformable bilinear sampling + depthwise =================
// 2 pixels per warp: lanes 0-15 pixel pA (4 ch/lane, LDG.128), lanes 16-31 pixel pA+1.
__global__ void __launch_bounds__(256) k2b_sample(const float* __restrict__ dw)
{
    const int b = blockIdx.y;
    const int wid = threadIdx.x >> 5, lane = threadIdx.x & 31;
    const int half = lane >> 4;                       // 0 -> pixel pA, 1 -> pixel pA+1
    const int pA = (blockIdx.x << 4) + (wid << 1);    // 8 warps * 2 px = 16 px per CTA
    const int p  = pA + half;
    const int y = p >> 7, x = p & 127;
    const int c0 = (lane & 15) << 2;                  // 4 channels per lane

    u64 dwp0[9], dwp1[9];
    #pragma unroll
    for (int k = 0; k < 9; k++) {
        dwp0[k] = pk2(dw[(c0 + 0) * 9 + k], dw[(c0 + 1) * 9 + k]);
        dwp1[k] = pk2(dw[(c0 + 2) * 9 + k], dw[(c0 + 3) * 9 + k]);
    }

    // offsets for both pixels of the pair (contiguous in g_off)
    const float* offA = g_off + (b * HW + pA) * 18;
    float ovA = (lane < 18) ? offA[lane] : 0.f;
    float ovB = (lane < 18) ? offA[18 + lane] : 0.f;

    const float* x1b = g_x1 + b * (HW * 64) + c0;
    u64 acc0 = 0ULL, acc1 = 0ULL;
    #pragma unroll
    for (int k = 0; k < 9; k++) {
        float dyA = __shfl_sync(0xffffffffu, ovA, 2 * k);
        float dxA = __shfl_sync(0xffffffffu, ovA, 2 * k + 1);
        float dyB = __shfl_sync(0xffffffffu, ovB, 2 * k);
        float dxB = __shfl_sync(0xffffffffu, ovB, 2 * k + 1);
        float dy = half ? dyB : dyA;
        float dx = half ? dxB : dxA;
        float py = (float)(y + k / 3 - 1) + dy;
        float px = (float)(x + (k % 3) - 1) + dx;
        float y0f = floorf(py), x0f = floorf(px);
        float wy = py - y0f, wx = px - x0f;
        int y0 = (int)y0f, x0 = (int)x0f;
        bool yv0 = (y0 >= 0) && (y0 < 128);
        bool yv1 = (y0 + 1 >= 0) && (y0 + 1 < 128);
        bool xv0 = (x0 >= 0) && (x0 < 128);
        bool xv1 = (x0 + 1 >= 0) && (x0 + 1 < 128);
        ulonglong2 z = make_ulonglong2(0ULL, 0ULL);
        ulonglong2 v00 = z, v01 = z, v10 = z, v11 = z;
        if (yv0 && xv0) v00 = *(const ulonglong2*)(x1b + (y0 * 128 + x0) * 64);
        if (yv0 && xv1) v01 = *(const ulonglong2*)(x1b + (y0 * 128 + x0 + 1) * 64);
        if (yv1 && xv0) v10 = *(const ulonglong2*)(x1b + ((y0 + 1) * 128 + x0) * 64);
        if (yv1 && xv1) v11 = *(const ulonglong2*)(x1b + ((y0 + 1) * 128 + x0 + 1) * 64);
        float omy = 1.f - wy, omx = 1.f - wx;
        u64 w11 = pk2(wy * wx,  wy * wx);
        u64 w10 = pk2(wy * omx, wy * omx);
        u64 w01 = pk2(omy * wx, omy * wx);
        u64 w00 = pk2(omy * omx, omy * omx);
        u64 s0 = f2mul(v11.x, w11);
        s0 = f2fma(v10.x, w10, s0);
        s0 = f2fma(v01.x, w01, s0);
        s0 = f2fma(v00.x, w00, s0);
        u64 s1 = f2mul(v11.y, w11);
        s1 = f2fma(v10.y, w10, s1);
        s1 = f2fma(v01.y, w01, s1);
        s1 = f2fma(v00.y, w00, s1);
        acc0 = f2fma(s0, dwp0[k], acc0);
        acc1 = f2fma(s1, dwp1[k], acc1);
    }
    *(ulonglong2*)(g_d + (b * HW + p) * 64 + c0) = make_ulonglong2(acc0, acc1);
}

// ================== K4: final 1x1 GEMM over concat(d, x2) + SiLU (mma.sync) ==================
__global__ void __launch_bounds__(256, 2) k4_mma(
    const float* __restrict__ w3, const float* __restrict__ s3, const float* __restrict__ b3,
    float* __restrict__ out)
{
    extern __shared__ char smem[];
    const int t = threadIdx.x, wid = t >> 5, lane = t & 31;
    const int g = lane >> 2, tg = lane & 3;
    const int wm = wid & 3, wn = wid >> 2;
    const int b = blockIdx.y, P = blockIdx.x << 7;

    float acc[2][8][4];
    #pragma unroll
    for (int i = 0; i < 2; i++)
        #pragma unroll
        for (int j = 0; j < 8; j++)
            #pragma unroll
            for (int q = 0; q < 4; q++) acc[i][j][q] = 0.f;

    #pragma unroll 1
    for (int s = 0; s < 2; s++) {
        const float* abase = (s ? g_x2 : g_d) + (b * HW + P) * 64;
        // A: NHWC rows direct (row = pixel, cols = 64 channels of this stage)
        for (int e = t; e < 2048; e += 256) {
            int r = e >> 4, c4 = (e & 15) << 2;
            float4 v = *(const float4*)(abase + r * 64 + c4);
            int off = r * TS + c4 * 2;
            *(uint32_t*)(smem + SM_A + off)     = h2pk(v.x, v.y);
            *(uint32_t*)(smem + SM_A + off + 4) = h2pk(v.z, v.w);
        }
        // B: w3 rows K-major direct (fp16)
        for (int e = t; e < 2048; e += 256) {
            int o = e >> 4, c4 = (e & 15) << 2;
            float4 v = *(const float4*)(w3 + o * 128 + s * 64 + c4);
            int off = o * TS + c4 * 2;
            *(uint32_t*)(smem + SM_B + off)     = h2pk(v.x, v.y);
            *(uint32_t*)(smem + SM_B + off + 4) = h2pk(v.z, v.w);
        }
        __syncthreads();
        mma_stage_compute(smem, wm, wn, g, tg, acc);
        __syncthreads();
    }

    // Epilogue: out is NCHW [b][o][p]
    #pragma unroll
    for (int i = 0; i < 2; i++) {
        #pragma unroll
        for (int j = 0; j < 8; j++) {
            int o = wn * 64 + j * 8 + 2 * tg;
            float sc0 = s3[o], sc1 = s3[o + 1];
            float bc0 = b3[o], bc1 = b3[o + 1];
            int p0 = P + wm * 32 + i * 16 + g;
            float* d0 = out + (b * 128 + o) * HW;
            float* d1 = out + (b * 128 + o + 1) * HW;
            d0[p0]     = silu_f(fmaf(acc[i][j][0], sc0, bc0));
            d1[p0]     = silu_f(fmaf(acc[i][j][1], sc1, bc1));
            d0[p0 + 8] = silu_f(fmaf(acc[i][j][2], sc0, bc0));
            d1[p0 + 8] = silu_f(fmaf(acc[i][j][3], sc1, bc1));
        }
    }
}

extern "C" void kernel_launch(void* const* d_in, const int* in_sizes, int n_in,
                              void* d_out, int out_size) {
    const float* x     = (const float*)d_in[0];
    const float* w1    = (const float*)d_in[1];
    const float* s1    = (const float*)d_in[2];
    const float* b1    = (const float*)d_in[3];
    const float* w2    = (const float*)d_in[4];
    const float* s2    = (const float*)d_in[5];
    const float* b2    = (const float*)d_in[6];
    const float* w3    = (const float*)d_in[7];
    const float* s3    = (const float*)d_in[8];
    const float* b3    = (const float*)d_in[9];
    const float* off_w = (const float*)d_in[10];
    const float* off_b = (const float*)d_in[11];
    const float* dw    = (const float*)d_in[12];
    float* out = (float*)d_out;

    cudaFuncSetAttribute(k1_mma, cudaFuncAttributeMaxDynamicSharedMemorySize, SM_MMA_TOTAL);
    cudaFuncSetAttribute(k2a_offconv, cudaFuncAttributeMaxDynamicSharedMemorySize, K2A_SMEM);
    cudaFuncSetAttribute(k4_mma, cudaFuncAttributeMaxDynamicSharedMemorySize, SM_MMA_TOTAL);

    dim3 g1(HW / 128, BATCH);
    k1_mma<<<g1, 256, SM_MMA_TOTAL>>>(x, w1, s1, b1, w2, s2, b2);

    dim3 g2a(128 / 32, 128 / 16, BATCH);
    k2a_offconv<<<g2a, 256, K2A_SMEM>>>(off_w, off_b);

    dim3 g2b(HW / 16, BATCH);
    k2b_sample<<<g2b, 256>>>(dw);

    dim3 g4(HW / 128, BATCH);
    k4_mma<<<g4, 256, SM_MMA_TOTAL>>>(w3, s3, b3, out);
}